// round 7
// baseline (speedup 1.0000x reference)
#include <cuda_runtime.h>
#include <math.h>

#define NB  2
#define T   4096
#define NH  16
#define D   64
#define HID 1024

// ---- scratch (static device globals; no runtime alloc) ----------------------
__device__ float g_q[(size_t)NB * NH * T * D];
__device__ float g_k[(size_t)NB * NH * T * D];
__device__ float g_v[(size_t)NB * NH * T * D];
__device__ int   g_gidx[NB * NH * 64 * 16];
__device__ int   g_lidx[NB * NH * 64 * 48];

// ---- QKV projection GEMM: out = A @ W^T + b, written to (n,h,t,d) -----------
__global__ __launch_bounds__(256) void gemm_proj(
    const float* __restrict__ A, const float* __restrict__ W,
    const float* __restrict__ bias, int which)
{
    float* dst = (which == 0) ? g_q : (which == 1) ? g_k : g_v;
    __shared__ __align__(16) float As[16][132];
    __shared__ __align__(16) float Ws[16][68];

    int tid = threadIdx.x;
    int m0 = blockIdx.y * 128, c0 = blockIdx.x * 64;
    int ty = tid >> 4, tx = tid & 15;

    float acc[8][4];
#pragma unroll
    for (int i = 0; i < 8; i++)
#pragma unroll
        for (int j = 0; j < 4; j++) acc[i][j] = 0.f;

    for (int k0 = 0; k0 < HID; k0 += 16) {
#pragma unroll
        for (int r = 0; r < 2; r++) {
            int lA = tid + r * 256;
            int row = lA >> 2, kq = (lA & 3) << 2;
            float4 v = *reinterpret_cast<const float4*>(A + (size_t)(m0 + row) * HID + k0 + kq);
            As[kq + 0][row] = v.x; As[kq + 1][row] = v.y;
            As[kq + 2][row] = v.z; As[kq + 3][row] = v.w;
        }
        {
            int row = tid >> 2, kq = (tid & 3) << 2;
            float4 v = *reinterpret_cast<const float4*>(W + (size_t)(c0 + row) * HID + k0 + kq);
            Ws[kq + 0][row] = v.x; Ws[kq + 1][row] = v.y;
            Ws[kq + 2][row] = v.z; Ws[kq + 3][row] = v.w;
        }
        __syncthreads();
#pragma unroll
        for (int kk = 0; kk < 16; kk++) {
            float4 a0 = *reinterpret_cast<const float4*>(&As[kk][ty * 4]);
            float4 a1 = *reinterpret_cast<const float4*>(&As[kk][64 + ty * 4]);
            float4 w0 = *reinterpret_cast<const float4*>(&Ws[kk][tx * 4]);
            float a[8] = {a0.x, a0.y, a0.z, a0.w, a1.x, a1.y, a1.z, a1.w};
            float w[4] = {w0.x, w0.y, w0.z, w0.w};
#pragma unroll
            for (int i = 0; i < 8; i++)
#pragma unroll
                for (int j = 0; j < 4; j++) acc[i][j] += a[i] * w[j];
        }
        __syncthreads();
    }

    float b0 = bias[c0 + tx * 4 + 0], b1 = bias[c0 + tx * 4 + 1];
    float b2 = bias[c0 + tx * 4 + 2], b3 = bias[c0 + tx * 4 + 3];
    int h = c0 >> 6;
#pragma unroll
    for (int i = 0; i < 8; i++) {
        int m = m0 + ((i < 4) ? (ty * 4 + i) : (64 + ty * 4 + i - 4));
        int n = m >> 12, t = m & (T - 1);
        float4 o = make_float4(acc[i][0] + b0, acc[i][1] + b1, acc[i][2] + b2, acc[i][3] + b3);
        *reinterpret_cast<float4*>(dst + (((size_t)(n * NH + h) * T + t) * D + tx * 4)) = o;
    }
}

// ---- norm-based top-k per (n,h,64-token block); stable argsort ranks --------
__global__ __launch_bounds__(64) void topk_kernel(
    const float* __restrict__ bq, const float* __restrict__ mask)
{
    int bid = blockIdx.x;
    int blk = bid & 63, h = (bid >> 6) & 15, n = bid >> 10;
    int i = threadIdx.x;
    int tok = blk * 64 + i;

    const float* krow = g_k + (((size_t)(n * NH + h)) * T + tok) * D;
    const float* bqh = bq + h * D;
    float nrm = 0.f;
#pragma unroll
    for (int d = 0; d < 64; d += 4) {
        float4 kv = *reinterpret_cast<const float4*>(krow + d);
        float4 bv = *reinterpret_cast<const float4*>(bqh + d);
        float x0 = kv.x + bv.x, x1 = kv.y + bv.y, x2 = kv.z + bv.z, x3 = kv.w + bv.w;
        nrm += x0 * x0 + x1 * x1 + x2 * x2 + x3 * x3;
    }
    if (mask[(size_t)n * T + tok] != 0.f) nrm = 0.f;

    __shared__ float sn[64];
    __shared__ int ssel[64];
    sn[i] = nrm;
    __syncthreads();

    int rank = 0;
    for (int j = 0; j < 64; j++) {
        float o = sn[j];
        rank += (o < nrm) || (o == nrm && j < i);
    }
    int sel = (rank >= 48);
    ssel[i] = sel;
    __syncthreads();

    int pos = 0;
    for (int j = 0; j < i; j++) pos += (ssel[j] == sel);
    if (sel) g_gidx[(size_t)(n * NH + h) * 1024 + blk * 16 + pos] = tok;
    else     g_lidx[(size_t)(n * NH + h) * 3072 + blk * 48 + pos] = tok;
}

// ---- fused local+global attention + LSE merge; one block per 64 queries -----
__global__ __launch_bounds__(256) void attn_kernel(
    const float* __restrict__ mask, float* __restrict__ out)
{
    __shared__ float qs[64 * 65];
    __shared__ float ks[32 * 65];
    __shared__ __align__(16) float vs[32 * 64];
    __shared__ float sc[32 * 65];
    __shared__ int klist[304];
    __shared__ float kmask[304];
    __shared__ float sf[64], linv[64], pm[64];

    int bid = blockIdx.x;
    int jb = bid & 63, h = (bid >> 6) & 15, n = bid >> 10;
    size_t hoff = ((size_t)(n * NH + h)) * T * D;
    const float* Q = g_q + hoff;
    const float* K = g_k + hoff;
    const float* V = g_v + hoff;
    const int* gI = g_gidx + (size_t)(n * NH + h) * 1024;
    const int* lI = g_lidx + (size_t)(n * NH + h) * 3072;
    const float* mrow = mask + (size_t)n * T;
    int tid = threadIdx.x;
    int t0 = jb * 64;

#pragma unroll
    for (int r = 0; r < 4; r++) {
        int idx = tid + r * 256;
        int qi = idx >> 4, dq = (idx & 15) << 2;
        float4 v = *reinterpret_cast<const float4*>(Q + (size_t)(t0 + qi) * D + dq);
        qs[qi * 65 + dq + 0] = v.x; qs[qi * 65 + dq + 1] = v.y;
        qs[qi * 65 + dq + 2] = v.z; qs[qi * 65 + dq + 3] = v.w;
    }

    int qq = tid & 15, kp = tid >> 4;     // phase A mapping
    int qB = tid & 63, dg = tid >> 6;     // phase B mapping

    float m_r = -1e30f, l_r = 0.f, lse_l = 0.f;
    float cacc[16], ctxl[16];

    for (int pass = 0; pass < 2; pass++) {
        int cnt;
        if (pass == 0) {
            int jl = jb >> 1;
            int wlo = (jl > 0) ? jl - 1 : 0;
            int whi = (jl < 31) ? jl + 1 : 31;
            cnt = (whi - wlo + 1) * 96 + 1;                 // + appended BOS key
            for (int p = tid; p < cnt; p += 256) {
                if (p == cnt - 1) { klist[p] = 0; kmask[p] = 0.f; }
                else {
                    int tok = lI[(wlo + p / 96) * 96 + (p % 96)];
                    klist[p] = tok; kmask[p] = mrow[tok];
                }
            }
        } else {
            int glo = (jb > 0) ? jb - 1 : 0;
            int ghi = (jb < 63) ? jb + 1 : 63;
            cnt = (ghi - glo + 1) * 16;
            if (tid < cnt) {
                int tok = gI[glo * 16 + tid];
                klist[tid] = tok; kmask[tid] = mrow[tok];
            }
        }
        __syncthreads();

        m_r = -1e30f; l_r = 0.f;
#pragma unroll
        for (int i = 0; i < 16; i++) cacc[i] = 0.f;

        for (int j0 = 0; j0 < cnt; j0 += 32) {
            int jt = min(32, cnt - j0);
#pragma unroll
            for (int r = 0; r < 2; r++) {
                int idx = tid + r * 256;
                int jj = idx >> 4, dq = (idx & 15) << 2;
                if (jj < jt) {
                    int tok = klist[j0 + jj];
                    float4 kv = *reinterpret_cast<const float4*>(K + (size_t)tok * D + dq);
                    ks[jj * 65 + dq + 0] = kv.x; ks[jj * 65 + dq + 1] = kv.y;
                    ks[jj * 65 + dq + 2] = kv.z; ks[jj * 65 + dq + 3] = kv.w;
                    float4 vv = *reinterpret_cast<const float4*>(V + (size_t)tok * D + dq);
                    *reinterpret_cast<float4*>(&vs[jj * 64 + dq]) = vv;
                }
            }
            __syncthreads();

            // phase A: 64q x 32k scores
            {
                int j0l = kp * 2;
                const float* k0p = &ks[j0l * 65];
                const float* k1p = &ks[(j0l + 1) * 65];
                const float* q0p = &qs[(qq * 4 + 0) * 65];
                const float* q1p = &qs[(qq * 4 + 1) * 65];
                const float* q2p = &qs[(qq * 4 + 2) * 65];
                const float* q3p = &qs[(qq * 4 + 3) * 65];
                float s00 = 0, s01 = 0, s10 = 0, s11 = 0, s20 = 0, s21 = 0, s30 = 0, s31 = 0;
#pragma unroll 16
                for (int d = 0; d < 64; d++) {
                    float kv0 = k0p[d], kv1 = k1p[d];
                    float qv0 = q0p[d], qv1 = q1p[d], qv2 = q2p[d], qv3 = q3p[d];
                    s00 += qv0 * kv0; s01 += qv0 * kv1;
                    s10 += qv1 * kv0; s11 += qv1 * kv1;
                    s20 += qv2 * kv0; s21 += qv2 * kv1;
                    s30 += qv3 * kv0; s31 += qv3 * kv1;
                }
                if (j0l < jt) {
                    float mv = kmask[j0 + j0l];
                    sc[j0l * 65 + qq * 4 + 0] = s00 * 0.125f + mv;
                    sc[j0l * 65 + qq * 4 + 1] = s10 * 0.125f + mv;
                    sc[j0l * 65 + qq * 4 + 2] = s20 * 0.125f + mv;
                    sc[j0l * 65 + qq * 4 + 3] = s30 * 0.125f + mv;
                }
                if (j0l + 1 < jt) {
                    float mv = kmask[j0 + j0l + 1];
                    sc[(j0l + 1) * 65 + qq * 4 + 0] = s01 * 0.125f + mv;
                    sc[(j0l + 1) * 65 + qq * 4 + 1] = s11 * 0.125f + mv;
                    sc[(j0l + 1) * 65 + qq * 4 + 2] = s21 * 0.125f + mv;
                    sc[(j0l + 1) * 65 + qq * 4 + 3] = s31 * 0.125f + mv;
                }
            }
            __syncthreads();

            // online softmax (one thread per query)
            if (tid < 64) {
                float mx = m_r;
                for (int j = 0; j < jt; j++) mx = fmaxf(mx, sc[j * 65 + tid]);
                float f = __expf(m_r - mx);
                float sum = l_r * f;
                for (int j = 0; j < jt; j++) {
                    float e = __expf(sc[j * 65 + tid] - mx);
                    sc[j * 65 + tid] = e;
                    sum += e;
                }
                m_r = mx; l_r = sum; sf[tid] = f;
            }
            __syncthreads();

            // phase B: context
            {
                float f = sf[qB];
#pragma unroll
                for (int i = 0; i < 16; i++) cacc[i] *= f;
                for (int j = 0; j < jt; j++) {
                    float p = sc[j * 65 + qB];
                    const float4* vr = reinterpret_cast<const float4*>(&vs[j * 64 + dg * 16]);
                    float4 v0 = vr[0], v1 = vr[1], v2 = vr[2], v3 = vr[3];
                    cacc[0] += p * v0.x; cacc[1] += p * v0.y; cacc[2] += p * v0.z; cacc[3] += p * v0.w;
                    cacc[4] += p * v1.x; cacc[5] += p * v1.y; cacc[6] += p * v1.z; cacc[7] += p * v1.w;
                    cacc[8] += p * v2.x; cacc[9] += p * v2.y; cacc[10] += p * v2.z; cacc[11] += p * v2.w;
                    cacc[12] += p * v3.x; cacc[13] += p * v3.y; cacc[14] += p * v3.z; cacc[15] += p * v3.w;
                }
            }
            __syncthreads();
        }

        if (tid < 64) {
            if (pass == 0) lse_l = m_r + __logf(l_r);
            else {
                float lse_g = m_r + __logf(l_r);
                pm[tid] = 1.f / (1.f + __expf(lse_g - lse_l));
            }
            linv[tid] = 1.f / l_r;
        }
        __syncthreads();

        if (pass == 0) {
            float il = linv[qB];
#pragma unroll
            for (int i = 0; i < 16; i++) ctxl[i] = cacc[i] * il;
        } else {
            float il = linv[qB], p = pm[qB];
            float o[16];
#pragma unroll
            for (int i = 0; i < 16; i++) {
                float cg = cacc[i] * il;
                o[i] = cg + p * (ctxl[i] - cg);
            }
            float4* o4 = reinterpret_cast<float4*>(
                out + ((size_t)(n * T + t0 + qB)) * HID + h * D + dg * 16);
            o4[0] = make_float4(o[0], o[1], o[2], o[3]);
            o4[1] = make_float4(o[4], o[5], o[6], o[7]);
            o4[2] = make_float4(o[8], o[9], o[10], o[11]);
            o4[3] = make_float4(o[12], o[13], o[14], o[15]);
        }
        __syncthreads();
    }
}

// ---- BOS row: full UNSCALED attention over all 4096 keys, overwrites t=0 ----
__global__ __launch_bounds__(256) void bos_kernel(
    const float* __restrict__ mask, float* __restrict__ out)
{
    __shared__ __align__(16) float q0s[64];
    __shared__ float sc[T];
    __shared__ float red[256];

    int h = blockIdx.x & 15, n = blockIdx.x >> 4;
    size_t hoff = ((size_t)(n * NH + h)) * T * D;
    const float* Q = g_q + hoff;
    const float* K = g_k + hoff;
    const float* V = g_v + hoff;
    const float* mrow = mask + (size_t)n * T;
    int tid = threadIdx.x;

    if (tid < 16)
        *reinterpret_cast<float4*>(&q0s[tid * 4]) =
            *reinterpret_cast<const float4*>(Q + tid * 4);
    __syncthreads();

    float lmax = -1e30f;
    for (int t = tid; t < T; t += 256) {
        const float* krow = K + (size_t)t * D;
        float s = 0.f;
#pragma unroll
        for (int d = 0; d < 64; d += 4) {
            float4 kv = *reinterpret_cast<const float4*>(krow + d);
            s += q0s[d] * kv.x + q0s[d + 1] * kv.y + q0s[d + 2] * kv.z + q0s[d + 3] * kv.w;
        }
        s += mrow[t];
        sc[t] = s;
        lmax = fmaxf(lmax, s);
    }
    red[tid] = lmax; __syncthreads();
    for (int o = 128; o > 0; o >>= 1) {
        if (tid < o) red[tid] = fmaxf(red[tid], red[tid + o]);
        __syncthreads();
    }
    float mx = red[0];
    __syncthreads();

    float lsum = 0.f;
    for (int t = tid; t < T; t += 256) {
        float e = __expf(sc[t] - mx);
        sc[t] = e;
        lsum += e;
    }
    red[tid] = lsum; __syncthreads();
    for (int o = 128; o > 0; o >>= 1) {
        if (tid < o) red[tid] += red[tid + o];
        __syncthreads();
    }
    float inv = 1.f / red[0];
    __syncthreads();

    int dd = tid & 63, dg = tid >> 6;
    float acc = 0.f;
    for (int t = dg * 1024; t < (dg + 1) * 1024; t++)
        acc += sc[t] * V[(size_t)t * D + dd];
    red[tid] = acc; __syncthreads();
    if (tid < 64) {
        float c = (red[tid] + red[tid + 64] + red[tid + 128] + red[tid + 192]) * inv;
        out[(size_t)n * T * HID + h * D + tid] = c;
    }
}

extern "C" void kernel_launch(void* const* d_in, const int* in_sizes, int n_in,
                              void* d_out, int out_size) {
    const float* hs   = (const float*)d_in[0];
    const float* mask = (const float*)d_in[1];
    const float* Wq = (const float*)d_in[2];
    const float* bq = (const float*)d_in[3];
    const float* Wk = (const float*)d_in[4];
    const float* bk = (const float*)d_in[5];
    const float* Wv = (const float*)d_in[6];
    const float* bv = (const float*)d_in[7];
    float* out = (float*)d_out;

    dim3 gg(HID / 64, (NB * T) / 128);
    gemm_proj<<<gg, 256>>>(hs, Wq, bq, 0);
    gemm_proj<<<gg, 256>>>(hs, Wk, bk, 1);
    gemm_proj<<<gg, 256>>>(hs, Wv, bv, 2);
    topk_kernel<<<NB * NH * 64, 64>>>(bq, mask);
    attn_kernel<<<NB * NH * 64, 256>>>(mask, out);
    bos_kernel<<<NB * NH, 256>>>(mask, out);
}

// round 10
// speedup vs baseline: 1.3780x; 1.3780x over previous
#include <cuda_runtime.h>
#include <cuda_bf16.h>
#include <cstdint>
#include <math.h>

#define NB  2
#define T   4096
#define NH  16
#define D   64
#define HID 1024
#define MTOT (NB * T)          // 8192 tokens

// ---- scratch (static device globals; no runtime alloc) ----------------------
__device__ float g_q[(size_t)NB * NH * T * D];
__device__ float g_k[(size_t)NB * NH * T * D];
__device__ float g_v[(size_t)NB * NH * T * D];
__device__ int   g_gidx[NB * NH * 64 * 16];
__device__ int   g_lidx[NB * NH * 64 * 48];
// bf16 split planes: x = hi + mid + lo
__device__ __align__(16) __nv_bfloat16 g_As[(size_t)3 * MTOT * HID];     // [plane][m][k]
__device__ __align__(16) __nv_bfloat16 g_Ws[(size_t)9 * HID * HID];      // [which*3+plane][c][k]

// ============ tcgen05 helpers: ONLY on arch-specific (sm_103a/sm_100a) =======
#if defined(__CUDA_ARCH_FEAT_SM103_ALL) || defined(__CUDA_ARCH_FEAT_SM100_ALL)
__device__ __forceinline__ uint32_t smem_u32(const void* p) {
    uint32_t a;
    asm("{ .reg .u64 t; cvta.to.shared.u64 t, %1; cvt.u32.u64 %0, t; }" : "=r"(a) : "l"(p));
    return a;
}
__device__ __forceinline__ uint32_t elect_one() {
    uint32_t p;
    asm volatile("{\n\t.reg .pred p;\n\telect.sync _|p, 0xFFFFFFFF;\n\t"
                 "selp.b32 %0, 1, 0, p;\n\t}" : "=r"(p));
    return p;
}
#define MBAR_INIT(a, c) asm volatile("mbarrier.init.shared.b64 [%0], %1;" :: "r"(a), "r"(c) : "memory")
#define MBAR_INVAL(a)   asm volatile("mbarrier.inval.shared.b64 [%0];" :: "r"(a) : "memory")
#define MBAR_WAIT(a, ph) do {                                                                 \
    uint32_t _m = (a), _p = (ph), _d;                                                         \
    asm volatile("{\n\t.reg .pred p;\n\t"                                                     \
        "mbarrier.try_wait.parity.acquire.cta.shared::cta.b64 p, [%1], %2;\n\t"               \
        "selp.b32 %0, 1, 0, p;\n\t}" : "=r"(_d) : "r"(_m), "r"(_p) : "memory");               \
    if (!_d) {                                                                                \
        asm volatile("{\n\t.reg .pred P1;\n\t"                                                \
            "WL_%=:\n\t"                                                                      \
            "mbarrier.try_wait.parity.acquire.cta.shared::cta.b64 P1, [%0], %1, 0x989680;\n\t"\
            "@P1 bra.uni WD_%=;\n\t"                                                          \
            "bra.uni WL_%=;\n\t"                                                              \
            "WD_%=:\n\t}" :: "r"(_m), "r"(_p) : "memory");                                    \
    }                                                                                         \
} while (0)

static constexpr uint64_t DESC_BASE_SW128 =
    (uint64_t(2) << 61) | (uint64_t(1) << 46) | (uint64_t(64) << 32) | (uint64_t(1) << 16);
__device__ __forceinline__ uint64_t make_desc(uint32_t addr) {
    return DESC_BASE_SW128 | ((uint64_t)(addr >> 4) & 0x3FFF);
}
__device__ __forceinline__ void mma_f16_ss(uint32_t d, uint64_t ad, uint64_t bd,
                                           uint32_t idesc, uint32_t en) {
    asm volatile("{\n\t.reg .pred p;\n\tsetp.ne.u32 p, %5, 0;\n\t"
        "tcgen05.mma.cta_group::1.kind::f16 [%0], %1, %2, %3, {%4, %4, %4, %4}, p;\n\t}"
        :: "r"(d), "l"(ad), "l"(bd), "r"(idesc), "r"(0u), "r"(en) : "memory");
}
#endif

// ---- bf16x3 split kernels ----------------------------------------------------
__global__ __launch_bounds__(256) void split_A(const float* __restrict__ A) {
    size_t n = (size_t)MTOT * HID;
    for (size_t i = blockIdx.x * 256ull + threadIdx.x; i < n; i += (size_t)gridDim.x * 256) {
        float x = A[i];
        __nv_bfloat16 h = __float2bfloat16(x);
        float r1 = x - __bfloat162float(h);
        __nv_bfloat16 m = __float2bfloat16(r1);
        float r2 = r1 - __bfloat162float(m);
        __nv_bfloat16 l = __float2bfloat16(r2);
        g_As[i] = h; g_As[n + i] = m; g_As[2 * n + i] = l;
    }
}
__global__ __launch_bounds__(256) void split_W(const float* __restrict__ W, int which) {
    size_t n = (size_t)HID * HID;
    __nv_bfloat16* dst = g_Ws + (size_t)which * 3 * n;
    for (size_t i = blockIdx.x * 256ull + threadIdx.x; i < n; i += (size_t)gridDim.x * 256) {
        float x = W[i];
        __nv_bfloat16 h = __float2bfloat16(x);
        float r1 = x - __bfloat162float(h);
        __nv_bfloat16 m = __float2bfloat16(r1);
        float r2 = r1 - __bfloat162float(m);
        __nv_bfloat16 l = __float2bfloat16(r2);
        dst[i] = h; dst[n + i] = m; dst[2 * n + i] = l;
    }
}

// ---- projection GEMM: 128x128 tile, out = A @ W^T + b ----------------------
// tcgen05 path (sm_103a cubin): bf16 split planes; K(which=1) 3-plane/6-prod,
// Q,V 2-plane/3-prod. Fallback path (compute_103 pass): fp32 FFMA tile GEMM.
#define SM_A 1024
#define SM_B (1024 + 3 * 16384)
#define SMEM_TOT (SM_B + 3 * 16384)
static constexpr uint32_t GEMM_IDESC =
    (1u << 4) | (1u << 7) | (1u << 10) | ((128u / 8) << 17) | ((128u / 16) << 24);

__global__ __launch_bounds__(256)
void gemm_tc(const float* __restrict__ A, const float* __restrict__ W,
             const float* __restrict__ bias, int which)
{
    extern __shared__ __align__(1024) char smem[];
    float* dst = (which == 0) ? g_q : (which == 1) ? g_k : g_v;
    int tid = threadIdx.x;
    int c0 = blockIdx.x * 128, m0 = blockIdx.y * 128;

#if defined(__CUDA_ARCH_FEAT_SM103_ALL) || defined(__CUDA_ARCH_FEAT_SM100_ALL)
    uint32_t sb = smem_u32(smem);
    int wid = tid >> 5, lane = tid & 31;
    int np = (which == 1) ? 3 : 2;        // planes loaded
    int nprod = (which == 1) ? 6 : 3;     // product MMAs per k-step
    const int pa6[6] = {0, 0, 1, 1, 0, 2};
    const int qb6[6] = {0, 1, 0, 1, 2, 0};

    if (wid == 0) {
        asm volatile("tcgen05.alloc.cta_group::1.sync.aligned.shared::cta.b32 [%0], %1;"
                     :: "r"(sb), "r"(128u) : "memory");
        asm volatile("tcgen05.relinquish_alloc_permit.cta_group::1.sync.aligned;");
        if (elect_one()) MBAR_INIT(sb + 8, 1);
    }
    __syncthreads();
    uint32_t tb;
    asm volatile("ld.shared.b32 %0, [%1];" : "=r"(tb) : "r"(sb));

    int pb = 0;
    for (int c = 0; c < 16; c++) {
        if (c > 0) { MBAR_WAIT(sb + 8, pb); pb ^= 1; }   // prev chunk's MMAs done
        int k0 = c * 64;
        for (int p = 0; p < np; p++) {                   // A planes, SW128
            const __nv_bfloat16* src = g_As + ((size_t)p * MTOT + m0) * HID + k0;
            char* dp = smem + SM_A + p * 16384;
            for (int i = tid; i < 1024; i += 256) {
                int row = i >> 3, q = i & 7;
                uint4 v = *reinterpret_cast<const uint4*>(
                    reinterpret_cast<const char*>(src + (size_t)row * HID) + q * 16);
                uint32_t off = row * 128 + q * 16;
                off ^= (off >> 3) & 0x70;
                *reinterpret_cast<uint4*>(dp + off) = v;
            }
        }
        for (int p = 0; p < np; p++) {                   // B planes (W rows c0..+127)
            const __nv_bfloat16* src = g_Ws + ((size_t)(which * 3 + p) * HID + c0) * HID + k0;
            char* dp = smem + SM_B + p * 16384;
            for (int i = tid; i < 1024; i += 256) {
                int row = i >> 3, q = i & 7;
                uint4 v = *reinterpret_cast<const uint4*>(
                    reinterpret_cast<const char*>(src + (size_t)row * HID) + q * 16);
                uint32_t off = row * 128 + q * 16;
                off ^= (off >> 3) & 0x70;
                *reinterpret_cast<uint4*>(dp + off) = v;
            }
        }
        asm volatile("fence.proxy.async.shared::cta;" ::: "memory");
        __syncthreads();

        if (wid == 0 && elect_one()) {
            for (int ks = 0; ks < 4; ks++)
                for (int cb = 0; cb < nprod; cb++) {
                    uint64_t ad = make_desc(sb + SM_A + pa6[cb] * 16384) + ks * 2;
                    uint64_t bd = make_desc(sb + SM_B + qb6[cb] * 16384) + ks * 2;
                    mma_f16_ss(tb, ad, bd, GEMM_IDESC,
                               (c == 0 && ks == 0 && cb == 0) ? 0u : 1u);
                }
            asm volatile(
                "tcgen05.commit.cta_group::1.mbarrier::arrive::one.shared::cluster.b64 [%0];"
                :: "r"(sb + 8) : "memory");
        }
    }
    MBAR_WAIT(sb + 8, pb);
    asm volatile("tcgen05.fence::after_thread_sync;" ::: "memory");

    // epilogue: warp w -> lanes (w&3)*32.., cols (w>>2)*64 .. +63
    int sp = wid & 3, cbase = (wid >> 2) * 64;
    int mg = m0 + sp * 32 + lane;
    int n = mg >> 12, t = mg & (T - 1);
    int h = (c0 + cbase) >> 6;
    float* orow = dst + ((size_t)(n * NH + h) * T + t) * D;
#pragma unroll
    for (int half = 0; half < 2; half++) {
        uint32_t r[32];
        asm volatile(
            "tcgen05.ld.sync.aligned.32x32b.x32.b32 "
            "{%0,%1,%2,%3,%4,%5,%6,%7,%8,%9,%10,%11,%12,%13,%14,%15,"
            "%16,%17,%18,%19,%20,%21,%22,%23,%24,%25,%26,%27,%28,%29,%30,%31}, [%32];"
            : "=r"(r[0]), "=r"(r[1]), "=r"(r[2]), "=r"(r[3]), "=r"(r[4]), "=r"(r[5]),
              "=r"(r[6]), "=r"(r[7]), "=r"(r[8]), "=r"(r[9]), "=r"(r[10]), "=r"(r[11]),
              "=r"(r[12]), "=r"(r[13]), "=r"(r[14]), "=r"(r[15]), "=r"(r[16]), "=r"(r[17]),
              "=r"(r[18]), "=r"(r[19]), "=r"(r[20]), "=r"(r[21]), "=r"(r[22]), "=r"(r[23]),
              "=r"(r[24]), "=r"(r[25]), "=r"(r[26]), "=r"(r[27]), "=r"(r[28]), "=r"(r[29]),
              "=r"(r[30]), "=r"(r[31])
            : "r"(tb + cbase + half * 32));
        asm volatile("tcgen05.wait::ld.sync.aligned;" ::: "memory");
#pragma unroll
        for (int g = 0; g < 8; g++) {
            int cc = c0 + cbase + half * 32 + g * 4;
            float4 o = make_float4(
                __uint_as_float(r[g * 4 + 0]) + bias[cc + 0],
                __uint_as_float(r[g * 4 + 1]) + bias[cc + 1],
                __uint_as_float(r[g * 4 + 2]) + bias[cc + 2],
                __uint_as_float(r[g * 4 + 3]) + bias[cc + 3]);
            *reinterpret_cast<float4*>(orow + half * 32 + g * 4) = o;
        }
    }
    __syncthreads();
    if (wid == 0) {
        if (elect_one()) MBAR_INVAL(sb + 8);
        asm volatile("tcgen05.dealloc.cta_group::1.sync.aligned.b32 %0, %1;"
                     :: "r"(tb), "r"(128u));
    }
#else
    // ---- FFMA fallback (compiled for non-'a' targets; correct, R7-class) ----
    float (*As)[132] = reinterpret_cast<float(*)[132]>(smem);
    float (*Bs)[132] = reinterpret_cast<float(*)[132]>(smem + 16 * 132 * 4);
    int ty = tid >> 4, tx = tid & 15;
    float acc[8][8];
#pragma unroll
    for (int i = 0; i < 8; i++)
#pragma unroll
        for (int j = 0; j < 8; j++) acc[i][j] = 0.f;

    for (int k0 = 0; k0 < HID; k0 += 16) {
#pragma unroll
        for (int r = 0; r < 2; r++) {
            int lA = tid + r * 256;
            int row = lA >> 2, kq = (lA & 3) << 2;
            float4 v = *reinterpret_cast<const float4*>(A + (size_t)(m0 + row) * HID + k0 + kq);
            As[kq + 0][row] = v.x; As[kq + 1][row] = v.y;
            As[kq + 2][row] = v.z; As[kq + 3][row] = v.w;
            float4 w = *reinterpret_cast<const float4*>(W + (size_t)(c0 + row) * HID + k0 + kq);
            Bs[kq + 0][row] = w.x; Bs[kq + 1][row] = w.y;
            Bs[kq + 2][row] = w.z; Bs[kq + 3][row] = w.w;
        }
        __syncthreads();
#pragma unroll
        for (int kk = 0; kk < 16; kk++) {
            float4 a0 = *reinterpret_cast<const float4*>(&As[kk][ty * 8]);
            float4 a1 = *reinterpret_cast<const float4*>(&As[kk][ty * 8 + 4]);
            float4 b0 = *reinterpret_cast<const float4*>(&Bs[kk][tx * 8]);
            float4 b1 = *reinterpret_cast<const float4*>(&Bs[kk][tx * 8 + 4]);
            float a[8] = {a0.x, a0.y, a0.z, a0.w, a1.x, a1.y, a1.z, a1.w};
            float b[8] = {b0.x, b0.y, b0.z, b0.w, b1.x, b1.y, b1.z, b1.w};
#pragma unroll
            for (int i = 0; i < 8; i++)
#pragma unroll
                for (int j = 0; j < 8; j++) acc[i][j] += a[i] * b[j];
        }
        __syncthreads();
    }
#pragma unroll
    for (int i = 0; i < 8; i++) {
        int m = m0 + ty * 8 + i;
        int n = m >> 12, t = m & (T - 1);
#pragma unroll
        for (int jq = 0; jq < 2; jq++) {
            int col = c0 + tx * 8 + jq * 4;
            int h = col >> 6, d = col & 63;
            float4 o = make_float4(acc[i][jq * 4 + 0] + bias[col + 0],
                                   acc[i][jq * 4 + 1] + bias[col + 1],
                                   acc[i][jq * 4 + 2] + bias[col + 2],
                                   acc[i][jq * 4 + 3] + bias[col + 3]);
            *reinterpret_cast<float4*>(dst + ((size_t)(n * NH + h) * T + t) * D + d) = o;
        }
    }
#endif
}

// ---- norm-based top-k per (n,h,64-token block); stable argsort ranks --------
__global__ __launch_bounds__(64) void topk_kernel(
    const float* __restrict__ bq, const float* __restrict__ mask)
{
    int bid = blockIdx.x;
    int blk = bid & 63, h = (bid >> 6) & 15, n = bid >> 10;
    int i = threadIdx.x;
    int tok = blk * 64 + i;

    const float* krow = g_k + (((size_t)(n * NH + h)) * T + tok) * D;
    const float* bqh = bq + h * D;
    float nrm = 0.f;
#pragma unroll
    for (int d = 0; d < 64; d += 4) {
        float4 kv = *reinterpret_cast<const float4*>(krow + d);
        float4 bv = *reinterpret_cast<const float4*>(bqh + d);
        float x0 = kv.x + bv.x, x1 = kv.y + bv.y, x2 = kv.z + bv.z, x3 = kv.w + bv.w;
        nrm += x0 * x0 + x1 * x1 + x2 * x2 + x3 * x3;
    }
    if (mask[(size_t)n * T + tok] != 0.f) nrm = 0.f;

    __shared__ float sn[64];
    __shared__ int ssel[64];
    sn[i] = nrm;
    __syncthreads();

    int rank = 0;
    for (int j = 0; j < 64; j++) {
        float o = sn[j];
        rank += (o < nrm) || (o == nrm && j < i);
    }
    int sel = (rank >= 48);
    ssel[i] = sel;
    __syncthreads();

    int pos = 0;
    for (int j = 0; j < i; j++) pos += (ssel[j] == sel);
    if (sel) g_gidx[(size_t)(n * NH + h) * 1024 + blk * 16 + pos] = tok;
    else     g_lidx[(size_t)(n * NH + h) * 3072 + blk * 48 + pos] = tok;
}

// ---- fused local+global attention + LSE merge; one block per 64 queries -----
__global__ __launch_bounds__(256) void attn_kernel(
    const float* __restrict__ mask, float* __restrict__ out)
{
    __shared__ float qs[64 * 65];
    __shared__ float ks[32 * 65];
    __shared__ __align__(16) float vs[32 * 64];
    __shared__ float sc[32 * 65];
    __shared__ int klist[304];
    __shared__ float kmask[304];
    __shared__ float sf[64], linv[64], pm[64];

    int bid = blockIdx.x;
    int jb = bid & 63, h = (bid >> 6) & 15, n = bid >> 10;
    size_t hoff = ((size_t)(n * NH + h)) * T * D;
    const float* Q = g_q + hoff;
    const float* K = g_k + hoff;
    const float* V = g_v + hoff;
    const int* gI = g_gidx + (size_t)(n * NH + h) * 1024;
    const int* lI = g_lidx + (size_t)(n * NH + h) * 3072;
    const float* mrow = mask + (size_t)n * T;
    int tid = threadIdx.x;
    int t0 = jb * 64;

#pragma unroll
    for (int r = 0; r < 4; r++) {
        int idx = tid + r * 256;
        int qi = idx >> 4, dq = (idx & 15) << 2;
        float4 v = *reinterpret_cast<const float4*>(Q + (size_t)(t0 + qi) * D + dq);
        qs[qi * 65 + dq + 0] = v.x; qs[qi * 65 + dq + 1] = v.y;
        qs[qi * 65 + dq + 2] = v.z; qs[qi * 65 + dq + 3] = v.w;
    }

    int qq = tid & 15, kp = tid >> 4;
    int qB = tid & 63, dg = tid >> 6;

    float m_r = -1e30f, l_r = 0.f, lse_l = 0.f;
    float cacc[16], ctxl[16];

    for (int pass = 0; pass < 2; pass++) {
        int cnt;
        if (pass == 0) {
            int jl = jb >> 1;
            int wlo = (jl > 0) ? jl - 1 : 0;
            int whi = (jl < 31) ? jl + 1 : 31;
            cnt = (whi - wlo + 1) * 96 + 1;
            for (int p = tid; p < cnt; p += 256) {
                if (p == cnt - 1) { klist[p] = 0; kmask[p] = 0.f; }
                else {
                    int tok = lI[(wlo + p / 96) * 96 + (p % 96)];
                    klist[p] = tok; kmask[p] = mrow[tok];
                }
            }
        } else {
            int glo = (jb > 0) ? jb - 1 : 0;
            int ghi = (jb < 63) ? jb + 1 : 63;
            cnt = (ghi - glo + 1) * 16;
            if (tid < cnt) {
                int tok = gI[glo * 16 + tid];
                klist[tid] = tok; kmask[tid] = mrow[tok];
            }
        }
        __syncthreads();

        m_r = -1e30f; l_r = 0.f;
#pragma unroll
        for (int i = 0; i < 16; i++) cacc[i] = 0.f;

        for (int j0 = 0; j0 < cnt; j0 += 32) {
            int jt = min(32, cnt - j0);
#pragma unroll
            for (int r = 0; r < 2; r++) {
                int idx = tid + r * 256;
                int jj = idx >> 4, dq = (idx & 15) << 2;
                if (jj < jt) {
                    int tok = klist[j0 + jj];
                    float4 kv = *reinterpret_cast<const float4*>(K + (size_t)tok * D + dq);
                    ks[jj * 65 + dq + 0] = kv.x; ks[jj * 65 + dq + 1] = kv.y;
                    ks[jj * 65 + dq + 2] = kv.z; ks[jj * 65 + dq + 3] = kv.w;
                    float4 vv = *reinterpret_cast<const float4*>(V + (size_t)tok * D + dq);
                    *reinterpret_cast<float4*>(&vs[jj * 64 + dq]) = vv;
                }
            }
            __syncthreads();

            {
                int j0l = kp * 2;
                const float* k0p = &ks[j0l * 65];
                const float* k1p = &ks[(j0l + 1) * 65];
                const float* q0p = &qs[(qq * 4 + 0) * 65];
                const float* q1p = &qs[(qq * 4 + 1) * 65];
                const float* q2p = &qs[(qq * 4 + 2) * 65];
                const float* q3p = &qs[(qq * 4 + 3) * 65];
                float s00 = 0, s01 = 0, s10 = 0, s11 = 0, s20 = 0, s21 = 0, s30 = 0, s31 = 0;
#pragma unroll 16
                for (int d = 0; d < 64; d++) {
                    float kv0 = k0p[d], kv1 = k1p[d];
                    float qv0 = q0p[d], qv1 = q1p[d], qv2 = q2p[d], qv3 = q3p[d];
                    s00 += qv0 * kv0; s01 += qv0 * kv1;
                    s10 += qv1 * kv0; s11 += qv1 * kv1;
                    s20 += qv2 * kv0; s21 += qv2 * kv1;
                    s30 += qv3 * kv0; s31 += qv3 * kv1;
                }
                if (j0l < jt) {
                    float mv = kmask[j0 + j0l];
                    sc[j0l * 65 + qq * 4 + 0] = s00 * 0.125f + mv;
                    sc[j0l * 65 + qq * 4 + 1] = s10 * 0.125f + mv;
                    sc[j0l * 65 + qq * 4 + 2] = s20 * 0.125f + mv;
                    sc[j0l * 65 + qq * 4 + 3] = s30 * 0.125f + mv;
                }
                if (j0l + 1 < jt) {
                    float mv = kmask[j0 + j0l + 1];
                    sc[(j0l + 1) * 65 + qq * 4 + 0] = s01 * 0.125f + mv;
                    sc[(j0l + 1) * 65 + qq * 4 + 1] = s11 * 0.125f + mv;
                    sc[(j0l + 1) * 65 + qq * 4 + 2] = s21 * 0.125f + mv;
                    sc[(j0l + 1) * 65 + qq * 4 + 3] = s31 * 0.125f + mv;
                }
            }
            __syncthreads();

            if (tid < 64) {
                float mx = m_r;
                for (int j = 0; j < jt; j++) mx = fmaxf(mx, sc[j * 65 + tid]);
                float f = __expf(m_r - mx);
                float sum = l_r * f;
                for (int j = 0; j < jt; j++) {
                    float e = __expf(sc[j * 65 + tid] - mx);
                    sc[j * 65 + tid] = e;
                    sum += e;
                }
                m_r = mx; l_r = sum; sf[tid] = f;
            }
            __syncthreads();

            {
                float f = sf[qB];
#pragma unroll
                for (int i = 0; i < 16; i++) cacc[i] *= f;
                for (int j = 0; j < jt; j++) {
                    float p = sc[j * 65 + qB];
                    const float4* vr = reinterpret_cast<const float4*>(&vs[j * 64 + dg * 16]);
                    float4 v0 = vr[0], v1 = vr[1], v2 = vr[2], v3 = vr[3];
                    cacc[0] += p * v0.x; cacc[1] += p * v0.y; cacc[2] += p * v0.z; cacc[3] += p * v0.w;
                    cacc[4] += p * v1.x; cacc[5] += p * v1.y; cacc[6] += p * v1.z; cacc[7] += p * v1.w;
                    cacc[8] += p * v2.x; cacc[9] += p * v2.y; cacc[10] += p * v2.z; cacc[11] += p * v2.w;
                    cacc[12] += p * v3.x; cacc[13] += p * v3.y; cacc[14] += p * v3.z; cacc[15] += p * v3.w;
                }
            }
            __syncthreads();
        }

        if (tid < 64) {
            if (pass == 0) lse_l = m_r + __logf(l_r);
            else {
                float lse_g = m_r + __logf(l_r);
                pm[tid] = 1.f / (1.f + __expf(lse_g - lse_l));
            }
            linv[tid] = 1.f / l_r;
        }
        __syncthreads();

        if (pass == 0) {
            float il = linv[qB];
#pragma unroll
            for (int i = 0; i < 16; i++) ctxl[i] = cacc[i] * il;
        } else {
            float il = linv[qB], p = pm[qB];
            float o[16];
#pragma unroll
            for (int i = 0; i < 16; i++) {
                float cg = cacc[i] * il;
                o[i] = cg + p * (ctxl[i] - cg);
            }
            float4* o4 = reinterpret_cast<float4*>(
                out + ((size_t)(n * T + t0 + qB)) * HID + h * D + dg * 16);
            o4[0] = make_float4(o[0], o[1], o[2], o[3]);
            o4[1] = make_float4(o[4], o[5], o[6], o[7]);
            o4[2] = make_float4(o[8], o[9], o[10], o[11]);
            o4[3] = make_float4(o[12], o[13], o[14], o[15]);
        }
        __syncthreads();
    }
}

// ---- BOS row: full UNSCALED attention over all 4096 keys, overwrites t=0 ----
__global__ __launch_bounds__(256) void bos_kernel(
    const float* __restrict__ mask, float* __restrict__ out)
{
    __shared__ __align__(16) float q0s[64];
    __shared__ float sc[T];
    __shared__ float red[256];

    int h = blockIdx.x & 15, n = blockIdx.x >> 4;
    size_t hoff = ((size_t)(n * NH + h)) * T * D;
    const float* Q = g_q + hoff;
    const float* K = g_k + hoff;
    const float* V = g_v + hoff;
    const float* mrow = mask + (size_t)n * T;
    int tid = threadIdx.x;

    if (tid < 16)
        *reinterpret_cast<float4*>(&q0s[tid * 4]) =
            *reinterpret_cast<const float4*>(Q + tid * 4);
    __syncthreads();

    float lmax = -1e30f;
    for (int t = tid; t < T; t += 256) {
        const float* krow = K + (size_t)t * D;
        float s = 0.f;
#pragma unroll
        for (int d = 0; d < 64; d += 4) {
            float4 kv = *reinterpret_cast<const float4*>(krow + d);
            s += q0s[d] * kv.x + q0s[d + 1] * kv.y + q0s[d + 2] * kv.z + q0s[d + 3] * kv.w;
        }
        s += mrow[t];
        sc[t] = s;
        lmax = fmaxf(lmax, s);
    }
    red[tid] = lmax; __syncthreads();
    for (int o = 128; o > 0; o >>= 1) {
        if (tid < o) red[tid] = fmaxf(red[tid], red[tid + o]);
        __syncthreads();
    }
    float mx = red[0];
    __syncthreads();

    float lsum = 0.f;
    for (int t = tid; t < T; t += 256) {
        float e = __expf(sc[t] - mx);
        sc[t] = e;
        lsum += e;
    }
    red[tid] = lsum; __syncthreads();
    for (int o = 128; o > 0; o >>= 1) {
        if (tid < o) red[tid] += red[tid + o];
        __syncthreads();
    }
    float inv = 1.f / red[0];
    __syncthreads();

    int dd = tid & 63, dg = tid >> 6;
    float acc = 0.f;
    for (int t = dg * 1024; t < (dg + 1) * 1024; t++)
        acc += sc[t] * V[(size_t)t * D + dd];
    red[tid] = acc; __syncthreads();
    if (tid < 64) {
        float c = (red[tid] + red[tid + 64] + red[tid + 128] + red[tid + 192]) * inv;
        out[(size_t)n * T * HID + h * D + tid] = c;
    }
}

extern "C" void kernel_launch(void* const* d_in, const int* in_sizes, int n_in,
                              void* d_out, int out_size) {
    const float* hs   = (const float*)d_in[0];
    const float* mask = (const float*)d_in[1];
    const float* Wq = (const float*)d_in[2];
    const float* bq = (const float*)d_in[3];
    const float* Wk = (const float*)d_in[4];
    const float* bk = (const float*)d_in[5];
    const float* Wv = (const float*)d_in[6];
    const float* bv = (const float*)d_in[7];
    float* out = (float*)d_out;

    cudaFuncSetAttribute(gemm_tc, cudaFuncAttributeMaxDynamicSharedMemorySize, SMEM_TOT);

    split_A<<<2048, 256>>>(hs);
    split_W<<<1024, 256>>>(Wq, 0);
    split_W<<<1024, 256>>>(Wk, 1);
    split_W<<<1024, 256>>>(Wv, 2);

    dim3 gg(HID / 128, MTOT / 128);
    gemm_tc<<<gg, 256, SMEM_TOT>>>(hs, Wq, bq, 0);
    gemm_tc<<<gg, 256, SMEM_TOT>>>(hs, Wk, bk, 1);
    gemm_tc<<<gg, 256, SMEM_TOT>>>(hs, Wv, bv, 2);

    topk_kernel<<<NB * NH * 64, 64>>>(bq, mask);
    attn_kernel<<<NB * NH * 64, 256>>>(mask, out);
    bos_kernel<<<NB * NH, 256>>>(mask, out);
}

// round 11
// speedup vs baseline: 1.4227x; 1.0324x over previous
#include <cuda_runtime.h>
#include <cuda_bf16.h>
#include <cstdint>
#include <math.h>

#define NB  2
#define T   4096
#define NH  16
#define D   64
#define HID 1024
#define MTOT (NB * T)          // 8192 tokens

// ---- scratch (static device globals; no runtime alloc) ----------------------
__device__ float g_q[(size_t)NB * NH * T * D];
__device__ float g_k[(size_t)NB * NH * T * D];
__device__ float g_v[(size_t)NB * NH * T * D];
__device__ int   g_gidx[NB * NH * 64 * 16];
__device__ int   g_lidx[NB * NH * 64 * 48];
// bf16 split planes: x = hi + mid + lo
__device__ __align__(16) __nv_bfloat16 g_As[(size_t)3 * MTOT * HID];     // [plane][m][k]
__device__ __align__(16) __nv_bfloat16 g_Ws[(size_t)9 * HID * HID];      // [which*3+plane][c][k]

// ---- packed fp32x2 helpers (FFMA2); fallback for non-'a' compile pass -------
typedef unsigned long long u64p;
__device__ __forceinline__ u64p pack2f(float x) {
    u64p r; asm("mov.b64 %0, {%1, %1};" : "=l"(r) : "f"(x)); return r;
}
__device__ __forceinline__ float2 unpack2f(u64p v) {
    float2 r; asm("mov.b64 {%0, %1}, %2;" : "=f"(r.x), "=f"(r.y) : "l"(v)); return r;
}
#if defined(__CUDA_ARCH_FEAT_SM103_ALL) || defined(__CUDA_ARCH_FEAT_SM100_ALL)
__device__ __forceinline__ u64p fma2(u64p a, u64p b, u64p c) {
    u64p d; asm("fma.rn.f32x2 %0, %1, %2, %3;" : "=l"(d) : "l"(a), "l"(b), "l"(c)); return d;
}
__device__ __forceinline__ u64p mul2(u64p a, u64p b) {
    u64p d; asm("mul.rn.f32x2 %0, %1, %2;" : "=l"(d) : "l"(a), "l"(b)); return d;
}
#else
__device__ __forceinline__ u64p fma2(u64p a, u64p b, u64p c) {
    float2 A = unpack2f(a), B = unpack2f(b), C = unpack2f(c);
    C.x = fmaf(A.x, B.x, C.x); C.y = fmaf(A.y, B.y, C.y);
    u64p r; asm("mov.b64 %0, {%1, %2};" : "=l"(r) : "f"(C.x), "f"(C.y)); return r;
}
__device__ __forceinline__ u64p mul2(u64p a, u64p b) {
    float2 A = unpack2f(a), B = unpack2f(b);
    A.x *= B.x; A.y *= B.y;
    u64p r; asm("mov.b64 %0, {%1, %2};" : "=l"(r) : "f"(A.x), "f"(A.y)); return r;
}
#endif

// ============ tcgen05 helpers: ONLY on arch-specific (sm_103a/sm_100a) =======
#if defined(__CUDA_ARCH_FEAT_SM103_ALL) || defined(__CUDA_ARCH_FEAT_SM100_ALL)
__device__ __forceinline__ uint32_t smem_u32(const void* p) {
    uint32_t a;
    asm("{ .reg .u64 t; cvta.to.shared.u64 t, %1; cvt.u32.u64 %0, t; }" : "=r"(a) : "l"(p));
    return a;
}
__device__ __forceinline__ uint32_t elect_one() {
    uint32_t p;
    asm volatile("{\n\t.reg .pred p;\n\telect.sync _|p, 0xFFFFFFFF;\n\t"
                 "selp.b32 %0, 1, 0, p;\n\t}" : "=r"(p));
    return p;
}
#define MBAR_INIT(a, c) asm volatile("mbarrier.init.shared.b64 [%0], %1;" :: "r"(a), "r"(c) : "memory")
#define MBAR_INVAL(a)   asm volatile("mbarrier.inval.shared.b64 [%0];" :: "r"(a) : "memory")
#define MBAR_WAIT(a, ph) do {                                                                 \
    uint32_t _m = (a), _p = (ph), _d;                                                         \
    asm volatile("{\n\t.reg .pred p;\n\t"                                                     \
        "mbarrier.try_wait.parity.acquire.cta.shared::cta.b64 p, [%1], %2;\n\t"               \
        "selp.b32 %0, 1, 0, p;\n\t}" : "=r"(_d) : "r"(_m), "r"(_p) : "memory");               \
    if (!_d) {                                                                                \
        asm volatile("{\n\t.reg .pred P1;\n\t"                                                \
            "WL_%=:\n\t"                                                                      \
            "mbarrier.try_wait.parity.acquire.cta.shared::cta.b64 P1, [%0], %1, 0x989680;\n\t"\
            "@P1 bra.uni WD_%=;\n\t"                                                          \
            "bra.uni WL_%=;\n\t"                                                              \
            "WD_%=:\n\t}" :: "r"(_m), "r"(_p) : "memory");                                    \
    }                                                                                         \
} while (0)

static constexpr uint64_t DESC_BASE_SW128 =
    (uint64_t(2) << 61) | (uint64_t(1) << 46) | (uint64_t(64) << 32) | (uint64_t(1) << 16);
__device__ __forceinline__ uint64_t make_desc(uint32_t addr) {
    return DESC_BASE_SW128 | ((uint64_t)(addr >> 4) & 0x3FFF);
}
__device__ __forceinline__ void mma_f16_ss(uint32_t d, uint64_t ad, uint64_t bd,
                                           uint32_t idesc, uint32_t en) {
    asm volatile("{\n\t.reg .pred p;\n\tsetp.ne.u32 p, %5, 0;\n\t"
        "tcgen05.mma.cta_group::1.kind::f16 [%0], %1, %2, %3, {%4, %4, %4, %4}, p;\n\t}"
        :: "r"(d), "l"(ad), "l"(bd), "r"(idesc), "r"(0u), "r"(en) : "memory");
}
#endif

// ---- bf16x3 split kernels ----------------------------------------------------
__global__ __launch_bounds__(256) void split_A(const float* __restrict__ A) {
    size_t n = (size_t)MTOT * HID;
    for (size_t i = blockIdx.x * 256ull + threadIdx.x; i < n; i += (size_t)gridDim.x * 256) {
        float x = A[i];
        __nv_bfloat16 h = __float2bfloat16(x);
        float r1 = x - __bfloat162float(h);
        __nv_bfloat16 m = __float2bfloat16(r1);
        float r2 = r1 - __bfloat162float(m);
        __nv_bfloat16 l = __float2bfloat16(r2);
        g_As[i] = h; g_As[n + i] = m; g_As[2 * n + i] = l;
    }
}
__global__ __launch_bounds__(256) void split_W(const float* __restrict__ W, int which) {
    size_t n = (size_t)HID * HID;
    __nv_bfloat16* dst = g_Ws + (size_t)which * 3 * n;
    for (size_t i = blockIdx.x * 256ull + threadIdx.x; i < n; i += (size_t)gridDim.x * 256) {
        float x = W[i];
        __nv_bfloat16 h = __float2bfloat16(x);
        float r1 = x - __bfloat162float(h);
        __nv_bfloat16 m = __float2bfloat16(r1);
        float r2 = r1 - __bfloat162float(m);
        __nv_bfloat16 l = __float2bfloat16(r2);
        dst[i] = h; dst[n + i] = m; dst[2 * n + i] = l;
    }
}

// ---- projection GEMM: 128x128 tile, out = A @ W^T + b ----------------------
#define SM_A 1024
#define SM_B (1024 + 3 * 16384)
#define SMEM_TOT (SM_B + 3 * 16384)
static constexpr uint32_t GEMM_IDESC =
    (1u << 4) | (1u << 7) | (1u << 10) | ((128u / 8) << 17) | ((128u / 16) << 24);

__global__ __launch_bounds__(256)
void gemm_tc(const float* __restrict__ A, const float* __restrict__ W,
             const float* __restrict__ bias, int which)
{
    extern __shared__ __align__(1024) char smem[];
    float* dst = (which == 0) ? g_q : (which == 1) ? g_k : g_v;
    int tid = threadIdx.x;
    int c0 = blockIdx.x * 128, m0 = blockIdx.y * 128;

#if defined(__CUDA_ARCH_FEAT_SM103_ALL) || defined(__CUDA_ARCH_FEAT_SM100_ALL)
    uint32_t sb = smem_u32(smem);
    int wid = tid >> 5, lane = tid & 31;
    int np = (which == 1) ? 3 : 2;        // planes loaded
    int nprod = (which == 1) ? 6 : 3;     // product MMAs per k-step
    const int pa6[6] = {0, 0, 1, 1, 0, 2};
    const int qb6[6] = {0, 1, 0, 1, 2, 0};

    if (wid == 0) {
        asm volatile("tcgen05.alloc.cta_group::1.sync.aligned.shared::cta.b32 [%0], %1;"
                     :: "r"(sb), "r"(128u) : "memory");
        asm volatile("tcgen05.relinquish_alloc_permit.cta_group::1.sync.aligned;");
        if (elect_one()) MBAR_INIT(sb + 8, 1);
    }
    __syncthreads();
    uint32_t tb;
    asm volatile("ld.shared.b32 %0, [%1];" : "=r"(tb) : "r"(sb));

    int pb = 0;
    for (int c = 0; c < 16; c++) {
        if (c > 0) { MBAR_WAIT(sb + 8, pb); pb ^= 1; }
        int k0 = c * 64;
        for (int p = 0; p < np; p++) {
            const __nv_bfloat16* src = g_As + ((size_t)p * MTOT + m0) * HID + k0;
            char* dp = smem + SM_A + p * 16384;
            for (int i = tid; i < 1024; i += 256) {
                int row = i >> 3, q = i & 7;
                uint4 v = *reinterpret_cast<const uint4*>(
                    reinterpret_cast<const char*>(src + (size_t)row * HID) + q * 16);
                uint32_t off = row * 128 + q * 16;
                off ^= (off >> 3) & 0x70;
                *reinterpret_cast<uint4*>(dp + off) = v;
            }
        }
        for (int p = 0; p < np; p++) {
            const __nv_bfloat16* src = g_Ws + ((size_t)(which * 3 + p) * HID + c0) * HID + k0;
            char* dp = smem + SM_B + p * 16384;
            for (int i = tid; i < 1024; i += 256) {
                int row = i >> 3, q = i & 7;
                uint4 v = *reinterpret_cast<const uint4*>(
                    reinterpret_cast<const char*>(src + (size_t)row * HID) + q * 16);
                uint32_t off = row * 128 + q * 16;
                off ^= (off >> 3) & 0x70;
                *reinterpret_cast<uint4*>(dp + off) = v;
            }
        }
        asm volatile("fence.proxy.async.shared::cta;" ::: "memory");
        __syncthreads();

        if (wid == 0 && elect_one()) {
            for (int ks = 0; ks < 4; ks++)
                for (int cb = 0; cb < nprod; cb++) {
                    uint64_t ad = make_desc(sb + SM_A + pa6[cb] * 16384) + ks * 2;
                    uint64_t bd = make_desc(sb + SM_B + qb6[cb] * 16384) + ks * 2;
                    mma_f16_ss(tb, ad, bd, GEMM_IDESC,
                               (c == 0 && ks == 0 && cb == 0) ? 0u : 1u);
                }
            asm volatile(
                "tcgen05.commit.cta_group::1.mbarrier::arrive::one.shared::cluster.b64 [%0];"
                :: "r"(sb + 8) : "memory");
        }
    }
    MBAR_WAIT(sb + 8, pb);
    asm volatile("tcgen05.fence::after_thread_sync;" ::: "memory");

    int sp = wid & 3, cbase = (wid >> 2) * 64;
    int mg = m0 + sp * 32 + lane;
    int n = mg >> 12, t = mg & (T - 1);
    int h = (c0 + cbase) >> 6;
    float* orow = dst + ((size_t)(n * NH + h) * T + t) * D;
#pragma unroll
    for (int half = 0; half < 2; half++) {
        uint32_t r[32];
        asm volatile(
            "tcgen05.ld.sync.aligned.32x32b.x32.b32 "
            "{%0,%1,%2,%3,%4,%5,%6,%7,%8,%9,%10,%11,%12,%13,%14,%15,"
            "%16,%17,%18,%19,%20,%21,%22,%23,%24,%25,%26,%27,%28,%29,%30,%31}, [%32];"
            : "=r"(r[0]), "=r"(r[1]), "=r"(r[2]), "=r"(r[3]), "=r"(r[4]), "=r"(r[5]),
              "=r"(r[6]), "=r"(r[7]), "=r"(r[8]), "=r"(r[9]), "=r"(r[10]), "=r"(r[11]),
              "=r"(r[12]), "=r"(r[13]), "=r"(r[14]), "=r"(r[15]), "=r"(r[16]), "=r"(r[17]),
              "=r"(r[18]), "=r"(r[19]), "=r"(r[20]), "=r"(r[21]), "=r"(r[22]), "=r"(r[23]),
              "=r"(r[24]), "=r"(r[25]), "=r"(r[26]), "=r"(r[27]), "=r"(r[28]), "=r"(r[29]),
              "=r"(r[30]), "=r"(r[31])
            : "r"(tb + cbase + half * 32));
        asm volatile("tcgen05.wait::ld.sync.aligned;" ::: "memory");
#pragma unroll
        for (int g = 0; g < 8; g++) {
            int cc = c0 + cbase + half * 32 + g * 4;
            float4 o = make_float4(
                __uint_as_float(r[g * 4 + 0]) + bias[cc + 0],
                __uint_as_float(r[g * 4 + 1]) + bias[cc + 1],
                __uint_as_float(r[g * 4 + 2]) + bias[cc + 2],
                __uint_as_float(r[g * 4 + 3]) + bias[cc + 3]);
            *reinterpret_cast<float4*>(orow + half * 32 + g * 4) = o;
        }
    }
    __syncthreads();
    if (wid == 0) {
        if (elect_one()) MBAR_INVAL(sb + 8);
        asm volatile("tcgen05.dealloc.cta_group::1.sync.aligned.b32 %0, %1;"
                     :: "r"(tb), "r"(128u));
    }
#else
    // ---- FFMA fallback (non-'a' targets) ----
    float (*As)[132] = reinterpret_cast<float(*)[132]>(smem);
    float (*Bs)[132] = reinterpret_cast<float(*)[132]>(smem + 16 * 132 * 4);
    int ty = tid >> 4, tx = tid & 15;
    float acc[8][8];
#pragma unroll
    for (int i = 0; i < 8; i++)
#pragma unroll
        for (int j = 0; j < 8; j++) acc[i][j] = 0.f;

    for (int k0 = 0; k0 < HID; k0 += 16) {
#pragma unroll
        for (int r = 0; r < 2; r++) {
            int lA = tid + r * 256;
            int row = lA >> 2, kq = (lA & 3) << 2;
            float4 v = *reinterpret_cast<const float4*>(A + (size_t)(m0 + row) * HID + k0 + kq);
            As[kq + 0][row] = v.x; As[kq + 1][row] = v.y;
            As[kq + 2][row] = v.z; As[kq + 3][row] = v.w;
            float4 w = *reinterpret_cast<const float4*>(W + (size_t)(c0 + row) * HID + k0 + kq);
            Bs[kq + 0][row] = w.x; Bs[kq + 1][row] = w.y;
            Bs[kq + 2][row] = w.z; Bs[kq + 3][row] = w.w;
        }
        __syncthreads();
#pragma unroll
        for (int kk = 0; kk < 16; kk++) {
            float4 a0 = *reinterpret_cast<const float4*>(&As[kk][ty * 8]);
            float4 a1 = *reinterpret_cast<const float4*>(&As[kk][ty * 8 + 4]);
            float4 b0 = *reinterpret_cast<const float4*>(&Bs[kk][tx * 8]);
            float4 b1 = *reinterpret_cast<const float4*>(&Bs[kk][tx * 8 + 4]);
            float a[8] = {a0.x, a0.y, a0.z, a0.w, a1.x, a1.y, a1.z, a1.w};
            float b[8] = {b0.x, b0.y, b0.z, b0.w, b1.x, b1.y, b1.z, b1.w};
#pragma unroll
            for (int i = 0; i < 8; i++)
#pragma unroll
                for (int j = 0; j < 8; j++) acc[i][j] += a[i] * b[j];
        }
        __syncthreads();
    }
#pragma unroll
    for (int i = 0; i < 8; i++) {
        int m = m0 + ty * 8 + i;
        int n = m >> 12, t = m & (T - 1);
#pragma unroll
        for (int jq = 0; jq < 2; jq++) {
            int col = c0 + tx * 8 + jq * 4;
            int h = col >> 6, d = col & 63;
            float4 o = make_float4(acc[i][jq * 4 + 0] + bias[col + 0],
                                   acc[i][jq * 4 + 1] + bias[col + 1],
                                   acc[i][jq * 4 + 2] + bias[col + 2],
                                   acc[i][jq * 4 + 3] + bias[col + 3]);
            *reinterpret_cast<float4*>(dst + ((size_t)(n * NH + h) * T + t) * D + d) = o;
        }
    }
#endif
}

// ---- norm-based top-k per (n,h,64-token block); stable argsort ranks --------
__global__ __launch_bounds__(64) void topk_kernel(
    const float* __restrict__ bq, const float* __restrict__ mask)
{
    int bid = blockIdx.x;
    int blk = bid & 63, h = (bid >> 6) & 15, n = bid >> 10;
    int i = threadIdx.x;
    int tok = blk * 64 + i;

    const float* krow = g_k + (((size_t)(n * NH + h)) * T + tok) * D;
    const float* bqh = bq + h * D;
    float nrm = 0.f;
#pragma unroll
    for (int d = 0; d < 64; d += 4) {
        float4 kv = *reinterpret_cast<const float4*>(krow + d);
        float4 bv = *reinterpret_cast<const float4*>(bqh + d);
        float x0 = kv.x + bv.x, x1 = kv.y + bv.y, x2 = kv.z + bv.z, x3 = kv.w + bv.w;
        nrm += x0 * x0 + x1 * x1 + x2 * x2 + x3 * x3;
    }
    if (mask[(size_t)n * T + tok] != 0.f) nrm = 0.f;

    __shared__ float sn[64];
    __shared__ int ssel[64];
    sn[i] = nrm;
    __syncthreads();

    int rank = 0;
    for (int j = 0; j < 64; j++) {
        float o = sn[j];
        rank += (o < nrm) || (o == nrm && j < i);
    }
    int sel = (rank >= 48);
    ssel[i] = sel;
    __syncthreads();

    int pos = 0;
    for (int j = 0; j < i; j++) pos += (ssel[j] == sel);
    if (sel) g_gidx[(size_t)(n * NH + h) * 1024 + blk * 16 + pos] = tok;
    else     g_lidx[(size_t)(n * NH + h) * 3072 + blk * 48 + pos] = tok;
}

// ---- fused local+global attention + LSE merge; one block per 64 queries -----
// qs:[d][q] s68, ks:[d][k] s34, vs:[k][d], sc:[k][q] s68. f32x2 packed math.
__global__ __launch_bounds__(256) void attn_kernel(
    const float* __restrict__ mask, float* __restrict__ out)
{
    __shared__ float qs[64 * 68];
    __shared__ float ks[64 * 34];
    __shared__ __align__(16) float vs[32 * 64];
    __shared__ float sc[32 * 68];
    __shared__ int klist[304];
    __shared__ float kmask[304];
    __shared__ float pm4[256], ps4[256];

    int bid = blockIdx.x;
    int jb = bid & 63, h = (bid >> 6) & 15, n = bid >> 10;
    size_t hoff = ((size_t)(n * NH + h)) * T * D;
    const float* Q = g_q + hoff;
    const float* K = g_k + hoff;
    const float* V = g_v + hoff;
    const int* gI = g_gidx + (size_t)(n * NH + h) * 1024;
    const int* lI = g_lidx + (size_t)(n * NH + h) * 3072;
    const float* mrow = mask + (size_t)n * T;
    int tid = threadIdx.x;
    int t0 = jb * 64;

    // load Q transposed: qs[d][q]
#pragma unroll
    for (int r = 0; r < 4; r++) {
        int idx = tid + r * 256;
        int qi = idx >> 4, dq = (idx & 15) << 2;
        float4 v = *reinterpret_cast<const float4*>(Q + (size_t)(t0 + qi) * D + dq);
        qs[(dq + 0) * 68 + qi] = v.x; qs[(dq + 1) * 68 + qi] = v.y;
        qs[(dq + 2) * 68 + qi] = v.z; qs[(dq + 3) * 68 + qi] = v.w;
    }

    int qq = tid & 15, kp = tid >> 4;     // phase A mapping
    int qB = tid & 63, dg = tid >> 6;     // softmax / phase B mapping

    float lse_l = 0.f;
    float ctxl[16];

    for (int pass = 0; pass < 2; pass++) {
        int cnt;
        if (pass == 0) {
            int jl = jb >> 1;
            int wlo = (jl > 0) ? jl - 1 : 0;
            int whi = (jl < 31) ? jl + 1 : 31;
            cnt = (whi - wlo + 1) * 96 + 1;                 // + appended BOS key
            for (int p = tid; p < cnt; p += 256) {
                if (p == cnt - 1) { klist[p] = 0; kmask[p] = 0.f; }
                else {
                    int tok = lI[(wlo + p / 96) * 96 + (p % 96)];
                    klist[p] = tok; kmask[p] = mrow[tok];
                }
            }
        } else {
            int glo = (jb > 0) ? jb - 1 : 0;
            int ghi = (jb < 63) ? jb + 1 : 63;
            cnt = (ghi - glo + 1) * 16;
            if (tid < cnt) {
                int tok = gI[glo * 16 + tid];
                klist[tid] = tok; kmask[tid] = mrow[tok];
            }
        }
        __syncthreads();

        float m_r = -1e30f, l_r = 0.f;
        u64p c01[8];
#pragma unroll
        for (int i = 0; i < 8; i++) c01[i] = 0ull;

        for (int j0 = 0; j0 < cnt; j0 += 32) {
            int jt = min(32, cnt - j0);
            // gather K (transposed) and V
#pragma unroll
            for (int r = 0; r < 2; r++) {
                int idx = tid + r * 256;
                int jj = idx >> 4, dq = (idx & 15) << 2;
                if (jj < jt) {
                    int tok = klist[j0 + jj];
                    float4 kv = *reinterpret_cast<const float4*>(K + (size_t)tok * D + dq);
                    ks[(dq + 0) * 34 + jj] = kv.x; ks[(dq + 1) * 34 + jj] = kv.y;
                    ks[(dq + 2) * 34 + jj] = kv.z; ks[(dq + 3) * 34 + jj] = kv.w;
                    float4 vv = *reinterpret_cast<const float4*>(V + (size_t)tok * D + dq);
                    *reinterpret_cast<float4*>(&vs[jj * 64 + dq]) = vv;
                }
            }
            __syncthreads();

            // phase A: 64q x 32k scores, packed over 2 keys
            {
                u64p acc0 = 0ull, acc1 = 0ull, acc2 = 0ull, acc3 = 0ull;
                const float* qsp = qs + qq * 4;
                const float* ksp = ks + kp * 2;
#pragma unroll 16
                for (int d = 0; d < 64; d++) {
                    u64p kk = *reinterpret_cast<const u64p*>(ksp + d * 34);
                    float4 qv = *reinterpret_cast<const float4*>(qsp + d * 68);
                    acc0 = fma2(pack2f(qv.x), kk, acc0);
                    acc1 = fma2(pack2f(qv.y), kk, acc1);
                    acc2 = fma2(pack2f(qv.z), kk, acc2);
                    acc3 = fma2(pack2f(qv.w), kk, acc3);
                }
                int k0l = kp * 2;
                float2 s0 = unpack2f(acc0), s1 = unpack2f(acc1);
                float2 s2 = unpack2f(acc2), s3 = unpack2f(acc3);
                if (k0l < jt) {
                    float mv = kmask[j0 + k0l];
                    sc[k0l * 68 + qq * 4 + 0] = s0.x * 0.125f + mv;
                    sc[k0l * 68 + qq * 4 + 1] = s1.x * 0.125f + mv;
                    sc[k0l * 68 + qq * 4 + 2] = s2.x * 0.125f + mv;
                    sc[k0l * 68 + qq * 4 + 3] = s3.x * 0.125f + mv;
                }
                if (k0l + 1 < jt) {
                    float mv = kmask[j0 + k0l + 1];
                    sc[(k0l + 1) * 68 + qq * 4 + 0] = s0.y * 0.125f + mv;
                    sc[(k0l + 1) * 68 + qq * 4 + 1] = s1.y * 0.125f + mv;
                    sc[(k0l + 1) * 68 + qq * 4 + 2] = s2.y * 0.125f + mv;
                    sc[(k0l + 1) * 68 + qq * 4 + 3] = s3.y * 0.125f + mv;
                }
            }
            __syncthreads();

            // distributed online softmax: thread (qB, dg) handles keys dg*8..+7
            {
                int kbase = dg * 8;
                float lm = -1e30f;
#pragma unroll
                for (int i = 0; i < 8; i++) {
                    int k = kbase + i;
                    if (k < jt) lm = fmaxf(lm, sc[k * 68 + qB]);
                }
                pm4[dg * 64 + qB] = lm;
                __syncthreads();
                float mx = fmaxf(fmaxf(pm4[qB], pm4[64 + qB]),
                                 fmaxf(pm4[128 + qB], pm4[192 + qB]));
                mx = fmaxf(m_r, mx);
                float f = __expf(m_r - mx);
                float psum = 0.f;
#pragma unroll
                for (int i = 0; i < 8; i++) {
                    int k = kbase + i;
                    if (k < jt) {
                        float e = __expf(sc[k * 68 + qB] - mx);
                        sc[k * 68 + qB] = e;
                        psum += e;
                    }
                }
                ps4[dg * 64 + qB] = psum;
                __syncthreads();
                l_r = l_r * f + (ps4[qB] + ps4[64 + qB]) + (ps4[128 + qB] + ps4[192 + qB]);
                m_r = mx;

                // phase B: rescale and accumulate context (packed)
                u64p ff = pack2f(f);
#pragma unroll
                for (int i = 0; i < 8; i++) c01[i] = mul2(c01[i], ff);
                const float* vbase = vs + dg * 16;
                for (int j = 0; j < jt; j++) {
                    u64p pp = pack2f(sc[j * 68 + qB]);
                    const u64p* vr = reinterpret_cast<const u64p*>(vbase + j * 64);
#pragma unroll
                    for (int i = 0; i < 8; i++) c01[i] = fma2(pp, vr[i], c01[i]);
                }
            }
            __syncthreads();
        }

        float lse = m_r + __logf(l_r);
        float il = 1.f / l_r;
        if (pass == 0) {
            lse_l = lse;
#pragma unroll
            for (int i = 0; i < 8; i++) {
                float2 c = unpack2f(c01[i]);
                ctxl[2 * i] = c.x * il; ctxl[2 * i + 1] = c.y * il;
            }
        } else {
            float p = 1.f / (1.f + __expf(lse - lse_l));
            float o[16];
#pragma unroll
            for (int i = 0; i < 8; i++) {
                float2 c = unpack2f(c01[i]);
                float cg0 = c.x * il, cg1 = c.y * il;
                o[2 * i] = cg0 + p * (ctxl[2 * i] - cg0);
                o[2 * i + 1] = cg1 + p * (ctxl[2 * i + 1] - cg1);
            }
            float4* o4 = reinterpret_cast<float4*>(
                out + ((size_t)(n * T + t0 + qB)) * HID + h * D + dg * 16);
            o4[0] = make_float4(o[0], o[1], o[2], o[3]);
            o4[1] = make_float4(o[4], o[5], o[6], o[7]);
            o4[2] = make_float4(o[8], o[9], o[10], o[11]);
            o4[3] = make_float4(o[12], o[13], o[14], o[15]);
        }
        __syncthreads();
    }
}

// ---- BOS row: full UNSCALED attention over all 4096 keys, overwrites t=0 ----
__global__ __launch_bounds__(256) void bos_kernel(
    const float* __restrict__ mask, float* __restrict__ out)
{
    __shared__ __align__(16) float q0s[64];
    __shared__ float sc[T];
    __shared__ float red[256];

    int h = blockIdx.x & 15, n = blockIdx.x >> 4;
    size_t hoff = ((size_t)(n * NH + h)) * T * D;
    const float* Q = g_q + hoff;
    const float* K = g_k + hoff;
    const float* V = g_v + hoff;
    const float* mrow = mask + (size_t)n * T;
    int tid = threadIdx.x;

    if (tid < 16)
        *reinterpret_cast<float4*>(&q0s[tid * 4]) =
            *reinterpret_cast<const float4*>(Q + tid * 4);
    __syncthreads();

    float lmax = -1e30f;
    for (int t = tid; t < T; t += 256) {
        const float* krow = K + (size_t)t * D;
        float s = 0.f;
#pragma unroll
        for (int d = 0; d < 64; d += 4) {
            float4 kv = *reinterpret_cast<const float4*>(krow + d);
            s += q0s[d] * kv.x + q0s[d + 1] * kv.y + q0s[d + 2] * kv.z + q0s[d + 3] * kv.w;
        }
        s += mrow[t];
        sc[t] = s;
        lmax = fmaxf(lmax, s);
    }
    red[tid] = lmax; __syncthreads();
    for (int o = 128; o > 0; o >>= 1) {
        if (tid < o) red[tid] = fmaxf(red[tid], red[tid + o]);
        __syncthreads();
    }
    float mx = red[0];
    __syncthreads();

    float lsum = 0.f;
    for (int t = tid; t < T; t += 256) {
        float e = __expf(sc[t] - mx);
        sc[t] = e;
        lsum += e;
    }
    red[tid] = lsum; __syncthreads();
    for (int o = 128; o > 0; o >>= 1) {
        if (tid < o) red[tid] += red[tid + o];
        __syncthreads();
    }
    float inv = 1.f / red[0];
    __syncthreads();

    int dd = tid & 63, dg = tid >> 6;
    float acc = 0.f;
    for (int t = dg * 1024; t < (dg + 1) * 1024; t++)
        acc += sc[t] * V[(size_t)t * D + dd];
    red[tid] = acc; __syncthreads();
    if (tid < 64) {
        float c = (red[tid] + red[tid + 64] + red[tid + 128] + red[tid + 192]) * inv;
        out[(size_t)n * T * HID + h * D + tid] = c;
    }
}

extern "C" void kernel_launch(void* const* d_in, const int* in_sizes, int n_in,
                              void* d_out, int out_size) {
    const float* hs   = (const float*)d_in[0];
    const float* mask = (const float*)d_in[1];
    const float* Wq = (const float*)d_in[2];
    const float* bq = (const float*)d_in[3];
    const float* Wk = (const float*)d_in[4];
    const float* bk = (const float*)d_in[5];
    const float* Wv = (const float*)d_in[6];
    const float* bv = (const float*)d_in[7];
    float* out = (float*)d_out;

    cudaFuncSetAttribute(gemm_tc, cudaFuncAttributeMaxDynamicSharedMemorySize, SMEM_TOT);

    split_A<<<2048, 256>>>(hs);
    split_W<<<1024, 256>>>(Wq, 0);
    split_W<<<1024, 256>>>(Wk, 1);
    split_W<<<1024, 256>>>(Wv, 2);

    dim3 gg(HID / 128, MTOT / 128);
    gemm_tc<<<gg, 256, SMEM_TOT>>>(hs, Wq, bq, 0);
    gemm_tc<<<gg, 256, SMEM_TOT>>>(hs, Wk, bk, 1);
    gemm_tc<<<gg, 256, SMEM_TOT>>>(hs, Wv, bv, 2);

    topk_kernel<<<NB * NH * 64, 64>>>(bq, mask);
    attn_kernel<<<NB * NH * 64, 256>>>(mask, out);
    bos_kernel<<<NB * NH, 256>>>(mask, out);
}

// round 17
// speedup vs baseline: 2.1931x; 1.5416x over previous
#include <cuda_runtime.h>
#include <cuda_bf16.h>
#include <cstdint>
#include <math.h>

#define NB  2
#define T   4096
#define NH  16
#define D   64
#define HID 1024
#define MTOT (NB * T)          // 8192 tokens

// ---- scratch (static device globals; no runtime alloc) ----------------------
__device__ float g_q[(size_t)NB * NH * T * D];
__device__ float g_k[(size_t)NB * NH * T * D];
__device__ float g_v[(size_t)NB * NH * T * D];
__device__ int   g_gidx[NB * NH * 64 * 16];
__device__ int   g_lidx[NB * NH * 64 * 48];
// bf16 split planes: x = hi + mid + lo
__device__ __align__(16) __nv_bfloat16 g_As[(size_t)3 * MTOT * HID];     // [plane][m][k]
__device__ __align__(16) __nv_bfloat16 g_Ws[(size_t)9 * HID * HID];      // [which*3+plane][c][k]

// ---- packed fp32x2 helpers (FFMA2); fallback for non-'a' compile pass -------
typedef unsigned long long u64p;
__device__ __forceinline__ u64p pack2f(float x) {
    u64p r; asm("mov.b64 %0, {%1, %1};" : "=l"(r) : "f"(x)); return r;
}
__device__ __forceinline__ float2 unpack2f(u64p v) {
    float2 r; asm("mov.b64 {%0, %1}, %2;" : "=f"(r.x), "=f"(r.y) : "l"(v)); return r;
}
#if defined(__CUDA_ARCH_FEAT_SM103_ALL) || defined(__CUDA_ARCH_FEAT_SM100_ALL)
__device__ __forceinline__ u64p fma2(u64p a, u64p b, u64p c) {
    u64p d; asm("fma.rn.f32x2 %0, %1, %2, %3;" : "=l"(d) : "l"(a), "l"(b), "l"(c)); return d;
}
__device__ __forceinline__ u64p mul2(u64p a, u64p b) {
    u64p d; asm("mul.rn.f32x2 %0, %1, %2;" : "=l"(d) : "l"(a), "l"(b)); return d;
}
#else
__device__ __forceinline__ u64p fma2(u64p a, u64p b, u64p c) {
    float2 A = unpack2f(a), B = unpack2f(b), C = unpack2f(c);
    C.x = fmaf(A.x, B.x, C.x); C.y = fmaf(A.y, B.y, C.y);
    u64p r; asm("mov.b64 %0, {%1, %2};" : "=l"(r) : "f"(C.x), "f"(C.y)); return r;
}
__device__ __forceinline__ u64p mul2(u64p a, u64p b) {
    float2 A = unpack2f(a), B = unpack2f(b);
    A.x *= B.x; A.y *= B.y;
    u64p r; asm("mov.b64 %0, {%1, %2};" : "=l"(r) : "f"(A.x), "f"(A.y)); return r;
}
#endif

// ---- cp.async helpers (sm_80+; valid in every compile pass) -----------------
__device__ __forceinline__ uint32_t smem_u32g(const void* p) {
    uint32_t a;
    asm("{ .reg .u64 t; cvta.to.shared.u64 t, %1; cvt.u32.u64 %0, t; }" : "=r"(a) : "l"(p));
    return a;
}
__device__ __forceinline__ void cp_async16(uint32_t dst, const void* src) {
    asm volatile("cp.async.cg.shared.global [%0], [%1], 16;" :: "r"(dst), "l"(src));
}
#define CP_COMMIT() asm volatile("cp.async.commit_group;" ::: "memory")
#define CP_WAIT0()  asm volatile("cp.async.wait_group 0;" ::: "memory")

// ============ tcgen05 helpers: ONLY on arch-specific (sm_103a/sm_100a) =======
#if defined(__CUDA_ARCH_FEAT_SM103_ALL) || defined(__CUDA_ARCH_FEAT_SM100_ALL)
__device__ __forceinline__ uint32_t elect_one() {
    uint32_t p;
    asm volatile("{\n\t.reg .pred p;\n\telect.sync _|p, 0xFFFFFFFF;\n\t"
                 "selp.b32 %0, 1, 0, p;\n\t}" : "=r"(p));
    return p;
}
#define MBAR_INIT(a, c) asm volatile("mbarrier.init.shared.b64 [%0], %1;" :: "r"(a), "r"(c) : "memory")
#define MBAR_INVAL(a)   asm volatile("mbarrier.inval.shared.b64 [%0];" :: "r"(a) : "memory")
#define MBAR_WAIT(a, ph) do {                                                                 \
    uint32_t _m = (a), _p = (ph), _d;                                                         \
    asm volatile("{\n\t.reg .pred p;\n\t"                                                     \
        "mbarrier.try_wait.parity.acquire.cta.shared::cta.b64 p, [%1], %2;\n\t"               \
        "selp.b32 %0, 1, 0, p;\n\t}" : "=r"(_d) : "r"(_m), "r"(_p) : "memory");               \
    if (!_d) {                                                                                \
        asm volatile("{\n\t.reg .pred P1;\n\t"                                                \
            "WL_%=:\n\t"                                                                      \
            "mbarrier.try_wait.parity.acquire.cta.shared::cta.b64 P1, [%0], %1, 0x989680;\n\t"\
            "@P1 bra.uni WD_%=;\n\t"                                                          \
            "bra.uni WL_%=;\n\t"                                                              \
            "WD_%=:\n\t}" :: "r"(_m), "r"(_p) : "memory");                                    \
    }                                                                                         \
} while (0)

static constexpr uint64_t DESC_BASE_SW128 =
    (uint64_t(2) << 61) | (uint64_t(1) << 46) | (uint64_t(64) << 32) | (uint64_t(1) << 16);
__device__ __forceinline__ uint64_t make_desc(uint32_t addr) {
    return DESC_BASE_SW128 | ((uint64_t)(addr >> 4) & 0x3FFF);
}
__device__ __forceinline__ void mma_f16_ss(uint32_t d, uint64_t ad, uint64_t bd,
                                           uint32_t idesc, uint32_t en) {
    asm volatile("{\n\t.reg .pred p;\n\tsetp.ne.u32 p, %5, 0;\n\t"
        "tcgen05.mma.cta_group::1.kind::f16 [%0], %1, %2, %3, {%4, %4, %4, %4}, p;\n\t}"
        :: "r"(d), "l"(ad), "l"(bd), "r"(idesc), "r"(0u), "r"(en) : "memory");
}
#endif

// ---- bf16x3 split kernels ----------------------------------------------------
__global__ __launch_bounds__(256) void split_A(const float* __restrict__ A) {
    size_t n = (size_t)MTOT * HID;
    for (size_t i = blockIdx.x * 256ull + threadIdx.x; i < n; i += (size_t)gridDim.x * 256) {
        float x = A[i];
        __nv_bfloat16 h = __float2bfloat16(x);
        float r1 = x - __bfloat162float(h);
        __nv_bfloat16 m = __float2bfloat16(r1);
        float r2 = r1 - __bfloat162float(m);
        __nv_bfloat16 l = __float2bfloat16(r2);
        g_As[i] = h; g_As[n + i] = m; g_As[2 * n + i] = l;
    }
}
__global__ __launch_bounds__(256) void split_W(const float* __restrict__ W, int which) {
    size_t n = (size_t)HID * HID;
    __nv_bfloat16* dst = g_Ws + (size_t)which * 3 * n;
    for (size_t i = blockIdx.x * 256ull + threadIdx.x; i < n; i += (size_t)gridDim.x * 256) {
        float x = W[i];
        __nv_bfloat16 h = __float2bfloat16(x);
        float r1 = x - __bfloat162float(h);
        __nv_bfloat16 m = __float2bfloat16(r1);
        float r2 = r1 - __bfloat162float(m);
        __nv_bfloat16 l = __float2bfloat16(r2);
        dst[i] = h; dst[n + i] = m; dst[2 * n + i] = l;
    }
}

// ---- projection GEMM: 128x128 tile, out = A @ W^T + b ----------------------
#define SM_A 1024
#define SM_B (1024 + 3 * 16384)
#define SMEM_TOT (SM_B + 3 * 16384)
static constexpr uint32_t GEMM_IDESC =
    (1u << 4) | (1u << 7) | (1u << 10) | ((128u / 8) << 17) | ((128u / 16) << 24);

__global__ __launch_bounds__(256)
void gemm_tc(const float* __restrict__ A, const float* __restrict__ W,
             const float* __restrict__ bias, int which)
{
    extern __shared__ __align__(1024) char smem[];
    float* dst = (which == 0) ? g_q : (which == 1) ? g_k : g_v;
    int tid = threadIdx.x;
    int c0 = blockIdx.x * 128, m0 = blockIdx.y * 128;

#if defined(__CUDA_ARCH_FEAT_SM103_ALL) || defined(__CUDA_ARCH_FEAT_SM100_ALL)
    uint32_t sb = smem_u32g(smem);
    int wid = tid >> 5, lane = tid & 31;
    int np = (which == 1) ? 3 : 2;        // planes loaded
    int nprod = (which == 1) ? 6 : 3;     // product MMAs per k-step
    const int pa6[6] = {0, 0, 1, 1, 0, 2};
    const int qb6[6] = {0, 1, 0, 1, 2, 0};

    if (wid == 0) {
        asm volatile("tcgen05.alloc.cta_group::1.sync.aligned.shared::cta.b32 [%0], %1;"
                     :: "r"(sb), "r"(128u) : "memory");
        asm volatile("tcgen05.relinquish_alloc_permit.cta_group::1.sync.aligned;");
        if (elect_one()) MBAR_INIT(sb + 8, 1);
    }
    __syncthreads();
    uint32_t tb;
    asm volatile("ld.shared.b32 %0, [%1];" : "=r"(tb) : "r"(sb));

    int pb = 0;
    for (int c = 0; c < 16; c++) {
        if (c > 0) { MBAR_WAIT(sb + 8, pb); pb ^= 1; }   // prev chunk's MMAs done
        int k0 = c * 64;
        for (int p = 0; p < np; p++) {                   // A planes via cp.async
            const __nv_bfloat16* src = g_As + ((size_t)p * MTOT + m0) * HID + k0;
            uint32_t db = sb + SM_A + p * 16384;
            for (int i = tid; i < 1024; i += 256) {
                int row = i >> 3, q = i & 7;
                uint32_t off = row * 128 + q * 16;
                off ^= (off >> 3) & 0x70;
                cp_async16(db + off,
                    reinterpret_cast<const char*>(src + (size_t)row * HID) + q * 16);
            }
        }
        for (int p = 0; p < np; p++) {                   // B planes via cp.async
            const __nv_bfloat16* src = g_Ws + ((size_t)(which * 3 + p) * HID + c0) * HID + k0;
            uint32_t db = sb + SM_B + p * 16384;
            for (int i = tid; i < 1024; i += 256) {
                int row = i >> 3, q = i & 7;
                uint32_t off = row * 128 + q * 16;
                off ^= (off >> 3) & 0x70;
                cp_async16(db + off,
                    reinterpret_cast<const char*>(src + (size_t)row * HID) + q * 16);
            }
        }
        CP_COMMIT();
        CP_WAIT0();
        asm volatile("fence.proxy.async.shared::cta;" ::: "memory");
        __syncthreads();

        if (wid == 0 && elect_one()) {
            for (int ks = 0; ks < 4; ks++)
                for (int cb = 0; cb < nprod; cb++) {
                    uint64_t ad = make_desc(sb + SM_A + pa6[cb] * 16384) + ks * 2;
                    uint64_t bd = make_desc(sb + SM_B + qb6[cb] * 16384) + ks * 2;
                    mma_f16_ss(tb, ad, bd, GEMM_IDESC,
                               (c == 0 && ks == 0 && cb == 0) ? 0u : 1u);
                }
            asm volatile(
                "tcgen05.commit.cta_group::1.mbarrier::arrive::one.shared::cluster.b64 [%0];"
                :: "r"(sb + 8) : "memory");
        }
    }
    MBAR_WAIT(sb + 8, pb);
    asm volatile("tcgen05.fence::after_thread_sync;" ::: "memory");

    int sp = wid & 3, cbase = (wid >> 2) * 64;
    int mg = m0 + sp * 32 + lane;
    int n = mg >> 12, t = mg & (T - 1);
    int h = (c0 + cbase) >> 6;
    float* orow = dst + ((size_t)(n * NH + h) * T + t) * D;
#pragma unroll
    for (int half = 0; half < 2; half++) {
        uint32_t r[32];
        asm volatile(
            "tcgen05.ld.sync.aligned.32x32b.x32.b32 "
            "{%0,%1,%2,%3,%4,%5,%6,%7,%8,%9,%10,%11,%12,%13,%14,%15,"
            "%16,%17,%18,%19,%20,%21,%22,%23,%24,%25,%26,%27,%28,%29,%30,%31}, [%32];"
            : "=r"(r[0]), "=r"(r[1]), "=r"(r[2]), "=r"(r[3]), "=r"(r[4]), "=r"(r[5]),
              "=r"(r[6]), "=r"(r[7]), "=r"(r[8]), "=r"(r[9]), "=r"(r[10]), "=r"(r[11]),
              "=r"(r[12]), "=r"(r[13]), "=r"(r[14]), "=r"(r[15]), "=r"(r[16]), "=r"(r[17]),
              "=r"(r[18]), "=r"(r[19]), "=r"(r[20]), "=r"(r[21]), "=r"(r[22]), "=r"(r[23]),
              "=r"(r[24]), "=r"(r[25]), "=r"(r[26]), "=r"(r[27]), "=r"(r[28]), "=r"(r[29]),
              "=r"(r[30]), "=r"(r[31])
            : "r"(tb + cbase + half * 32));
        asm volatile("tcgen05.wait::ld.sync.aligned;" ::: "memory");
#pragma unroll
        for (int g = 0; g < 8; g++) {
            int cc = c0 + cbase + half * 32 + g * 4;
            float4 o = make_float4(
                __uint_as_float(r[g * 4 + 0]) + bias[cc + 0],
                __uint_as_float(r[g * 4 + 1]) + bias[cc + 1],
                __uint_as_float(r[g * 4 + 2]) + bias[cc + 2],
                __uint_as_float(r[g * 4 + 3]) + bias[cc + 3]);
            *reinterpret_cast<float4*>(orow + half * 32 + g * 4) = o;
        }
    }
    __syncthreads();
    if (wid == 0) {
        if (elect_one()) MBAR_INVAL(sb + 8);
        asm volatile("tcgen05.dealloc.cta_group::1.sync.aligned.b32 %0, %1;"
                     :: "r"(tb), "r"(128u));
    }
#else
    // ---- FFMA fallback (non-'a' targets) ----
    float (*As)[132] = reinterpret_cast<float(*)[132]>(smem);
    float (*Bs)[132] = reinterpret_cast<float(*)[132]>(smem + 16 * 132 * 4);
    int ty = tid >> 4, tx = tid & 15;
    float acc[8][8];
#pragma unroll
    for (int i = 0; i < 8; i++)
#pragma unroll
        for (int j = 0; j < 8; j++) acc[i][j] = 0.f;

    for (int k0 = 0; k0 < HID; k0 += 16) {
#pragma unroll
        for (int r = 0; r < 2; r++) {
            int lA = tid + r * 256;
            int row = lA >> 2, kq = (lA & 3) << 2;
            float4 v = *reinterpret_cast<const float4*>(A + (size_t)(m0 + row) * HID + k0 + kq);
            As[kq + 0][row] = v.x; As[kq + 1][row] = v.y;
            As[kq + 2][row] = v.z; As[kq + 3][row] = v.w;
            float4 w = *reinterpret_cast<const float4*>(W + (size_t)(c0 + row) * HID + k0 + kq);
            Bs[kq + 0][row] = w.x; Bs[kq + 1][row] = w.y;
            Bs[kq + 2][row] = w.z; Bs[kq + 3][row] = w.w;
        }
        __syncthreads();
#pragma unroll
        for (int kk = 0; kk < 16; kk++) {
            float4 a0 = *reinterpret_cast<const float4*>(&As[kk][ty * 8]);
            float4 a1 = *reinterpret_cast<const float4*>(&As[kk][ty * 8 + 4]);
            float4 b0 = *reinterpret_cast<const float4*>(&Bs[kk][tx * 8]);
            float4 b1 = *reinterpret_cast<const float4*>(&Bs[kk][tx * 8 + 4]);
            float a[8] = {a0.x, a0.y, a0.z, a0.w, a1.x, a1.y, a1.z, a1.w};
            float b[8] = {b0.x, b0.y, b0.z, b0.w, b1.x, b1.y, b1.z, b1.w};
#pragma unroll
            for (int i = 0; i < 8; i++)
#pragma unroll
                for (int j = 0; j < 8; j++) acc[i][j] += a[i] * b[j];
        }
        __syncthreads();
    }
#pragma unroll
    for (int i = 0; i < 8; i++) {
        int m = m0 + ty * 8 + i;
        int n = m >> 12, t = m & (T - 1);
#pragma unroll
        for (int jq = 0; jq < 2; jq++) {
            int col = c0 + tx * 8 + jq * 4;
            int h = col >> 6, d = col & 63;
            float4 o = make_float4(acc[i][jq * 4 + 0] + bias[col + 0],
                                   acc[i][jq * 4 + 1] + bias[col + 1],
                                   acc[i][jq * 4 + 2] + bias[col + 2],
                                   acc[i][jq * 4 + 3] + bias[col + 3]);
            *reinterpret_cast<float4*>(dst + ((size_t)(n * NH + h) * T + t) * D + d) = o;
        }
    }
#endif
}

// ---- norm-based top-k per (n,h,64-token block); stable argsort ranks --------
__global__ __launch_bounds__(64) void topk_kernel(
    const float* __restrict__ bq, const float* __restrict__ mask)
{
    int bid = blockIdx.x;
    int blk = bid & 63, h = (bid >> 6) & 15, n = bid >> 10;
    int i = threadIdx.x;
    int tok = blk * 64 + i;

    const float* krow = g_k + (((size_t)(n * NH + h)) * T + tok) * D;
    const float* bqh = bq + h * D;
    float nrm = 0.f;
#pragma unroll
    for (int d = 0; d < 64; d += 4) {
        float4 kv = *reinterpret_cast<const float4*>(krow + d);
        float4 bv = *reinterpret_cast<const float4*>(bqh + d);
        float x0 = kv.x + bv.x, x1 = kv.y + bv.y, x2 = kv.z + bv.z, x3 = kv.w + bv.w;
        nrm += x0 * x0 + x1 * x1 + x2 * x2 + x3 * x3;
    }
    if (mask[(size_t)n * T + tok] != 0.f) nrm = 0.f;

    __shared__ float sn[64];
    __shared__ int ssel[64];
    sn[i] = nrm;
    __syncthreads();

    int rank = 0;
    for (int j = 0; j < 64; j++) {
        float o = sn[j];
        rank += (o < nrm) || (o == nrm && j < i);
    }
    int sel = (rank >= 48);
    ssel[i] = sel;
    __syncthreads();

    int pos = 0;
    for (int j = 0; j < i; j++) pos += (ssel[j] == sel);
    if (sel) g_gidx[(size_t)(n * NH + h) * 1024 + blk * 16 + pos] = tok;
    else     g_lidx[(size_t)(n * NH + h) * 3072 + blk * 48 + pos] = tok;
}

// ---- fused local+global attention + LSE merge; one block per 64 queries -----
__global__ __launch_bounds__(256) void attn_kernel(
    const float* __restrict__ mask, float* __restrict__ out)
{
    __shared__ float qs[64 * 68];
    __shared__ float ks[64 * 34];
    __shared__ __align__(16) float vs[32 * 64];
    __shared__ float sc[32 * 68];
    __shared__ int klist[304];
    __shared__ float kmask[304];
    __shared__ float pm4[256], ps4[256];

    int bid = blockIdx.x;
    int jb = bid & 63, h = (bid >> 6) & 15, n = bid >> 10;
    size_t hoff = ((size_t)(n * NH + h)) * T * D;
    const float* Q = g_q + hoff;
    const float* K = g_k + hoff;
    const float* V = g_v + hoff;
    const int* gI = g_gidx + (size_t)(n * NH + h) * 1024;
    const int* lI = g_lidx + (size_t)(n * NH + h) * 3072;
    const float* mrow = mask + (size_t)n * T;
    int tid = threadIdx.x;
    int t0 = jb * 64;

#pragma unroll
    for (int r = 0; r < 4; r++) {
        int idx = tid + r * 256;
        int qi = idx >> 4, dq = (idx & 15) << 2;
        float4 v = *reinterpret_cast<const float4*>(Q + (size_t)(t0 + qi) * D + dq);
        qs[(dq + 0) * 68 + qi] = v.x; qs[(dq + 1) * 68 + qi] = v.y;
        qs[(dq + 2) * 68 + qi] = v.z; qs[(dq + 3) * 68 + qi] = v.w;
    }

    int qq = tid & 15, kp = tid >> 4;     // phase A mapping
    int qB = tid & 63, dg = tid >> 6;     // softmax / phase B mapping

    float lse_l = 0.f;
    float ctxl[16];

    for (int pass = 0; pass < 2; pass++) {
        int cnt;
        if (pass == 0) {
            int jl = jb >> 1;
            int wlo = (jl > 0) ? jl - 1 : 0;
            int whi = (jl < 31) ? jl + 1 : 31;
            cnt = (whi - wlo + 1) * 96 + 1;                 // + appended BOS key
            for (int p = tid; p < cnt; p += 256) {
                if (p == cnt - 1) { klist[p] = 0; kmask[p] = 0.f; }
                else {
                    int tok = lI[(wlo + p / 96) * 96 + (p % 96)];
                    klist[p] = tok; kmask[p] = mrow[tok];
                }
            }
        } else {
            int glo = (jb > 0) ? jb - 1 : 0;
            int ghi = (jb < 63) ? jb + 1 : 63;
            cnt = (ghi - glo + 1) * 16;
            if (tid < cnt) {
                int tok = gI[glo * 16 + tid];
                klist[tid] = tok; kmask[tid] = mrow[tok];
            }
        }
        __syncthreads();

        float m_r = -1e30f, l_r = 0.f;
        u64p c01[8];
#pragma unroll
        for (int i = 0; i < 8; i++) c01[i] = 0ull;

        for (int j0 = 0; j0 < cnt; j0 += 32) {
            int jt = min(32, cnt - j0);
#pragma unroll
            for (int r = 0; r < 2; r++) {
                int idx = tid + r * 256;
                int jj = idx >> 4, dq = (idx & 15) << 2;
                if (jj < jt) {
                    int tok = klist[j0 + jj];
                    float4 kv = *reinterpret_cast<const float4*>(K + (size_t)tok * D + dq);
                    ks[(dq + 0) * 34 + jj] = kv.x; ks[(dq + 1) * 34 + jj] = kv.y;
                    ks[(dq + 2) * 34 + jj] = kv.z; ks[(dq + 3) * 34 + jj] = kv.w;
                    float4 vv = *reinterpret_cast<const float4*>(V + (size_t)tok * D + dq);
                    *reinterpret_cast<float4*>(&vs[jj * 64 + dq]) = vv;
                }
            }
            __syncthreads();

            // phase A: 64q x 32k scores, packed over 2 keys
            {
                u64p acc0 = 0ull, acc1 = 0ull, acc2 = 0ull, acc3 = 0ull;
                const float* qsp = qs + qq * 4;
                const float* ksp = ks + kp * 2;
#pragma unroll 16
                for (int d = 0; d < 64; d++) {
                    u64p kk = *reinterpret_cast<const u64p*>(ksp + d * 34);
                    float4 qv = *reinterpret_cast<const float4*>(qsp + d * 68);
                    acc0 = fma2(pack2f(qv.x), kk, acc0);
                    acc1 = fma2(pack2f(qv.y), kk, acc1);
                    acc2 = fma2(pack2f(qv.z), kk, acc2);
                    acc3 = fma2(pack2f(qv.w), kk, acc3);
                }
                int k0l = kp * 2;
                float2 s0 = unpack2f(acc0), s1 = unpack2f(acc1);
                float2 s2 = unpack2f(acc2), s3 = unpack2f(acc3);
                if (k0l < jt) {
                    float mv = kmask[j0 + k0l];
                    sc[k0l * 68 + qq * 4 + 0] = s0.x * 0.125f + mv;
                    sc[k0l * 68 + qq * 4 + 1] = s1.x * 0.125f + mv;
                    sc[k0l * 68 + qq * 4 + 2] = s2.x * 0.125f + mv;
                    sc[k0l * 68 + qq * 4 + 3] = s3.x * 0.125f + mv;
                }
                if (k0l + 1 < jt) {
                    float mv = kmask[j0 + k0l + 1];
                    sc[(k0l + 1) * 68 + qq * 4 + 0] = s0.y * 0.125f + mv;
                    sc[(k0l + 1) * 68 + qq * 4 + 1] = s1.y * 0.125f + mv;
                    sc[(k0l + 1) * 68 + qq * 4 + 2] = s2.y * 0.125f + mv;
                    sc[(k0l + 1) * 68 + qq * 4 + 3] = s3.y * 0.125f + mv;
                }
            }
            __syncthreads();

            // one-sync softmax: per-group (max, expsum); sc holds exp(s - lm_g)
            {
                int kbase = dg * 8;
                float lm = -1e30f;
#pragma unroll
                for (int i = 0; i < 8; i++) {
                    int k = kbase + i;
                    if (k < jt) lm = fmaxf(lm, sc[k * 68 + qB]);
                }
                float psum = 0.f;
#pragma unroll
                for (int i = 0; i < 8; i++) {
                    int k = kbase + i;
                    if (k < jt) {
                        float e = __expf(sc[k * 68 + qB] - lm);
                        sc[k * 68 + qB] = e;
                        psum += e;
                    }
                }
                pm4[dg * 64 + qB] = lm;
                ps4[dg * 64 + qB] = psum;
                __syncthreads();

                float g0 = pm4[qB], g1 = pm4[64 + qB], g2 = pm4[128 + qB], g3 = pm4[192 + qB];
                float mx = fmaxf(fmaxf(g0, g1), fmaxf(g2, g3));
                mx = fmaxf(m_r, mx);
                float f = __expf(m_r - mx);
                float fg0 = __expf(g0 - mx), fg1 = __expf(g1 - mx);
                float fg2 = __expf(g2 - mx), fg3 = __expf(g3 - mx);
                l_r = l_r * f + ps4[qB] * fg0 + ps4[64 + qB] * fg1
                              + ps4[128 + qB] * fg2 + ps4[192 + qB] * fg3;
                m_r = mx;

                u64p ff = pack2f(f);
#pragma unroll
                for (int i = 0; i < 8; i++) c01[i] = mul2(c01[i], ff);
                const float* vbase = vs + dg * 16;
                float fgs[4] = {fg0, fg1, fg2, fg3};
#pragma unroll
                for (int jg = 0; jg < 4; jg++) {
                    int jbeg = jg * 8;
                    if (jbeg >= jt) break;
                    int jend = min(jbeg + 8, jt);
                    float fgv = fgs[jg];
                    for (int j = jbeg; j < jend; j++) {
                        u64p pp = pack2f(sc[j * 68 + qB] * fgv);
                        const ulonglong2* vr =
                            reinterpret_cast<const ulonglong2*>(vbase + j * 64);
                        ulonglong2 v0 = vr[0], v1 = vr[1], v2 = vr[2], v3 = vr[3];
                        c01[0] = fma2(pp, v0.x, c01[0]); c01[1] = fma2(pp, v0.y, c01[1]);
                        c01[2] = fma2(pp, v1.x, c01[2]); c01[3] = fma2(pp, v1.y, c01[3]);
                        c01[4] = fma2(pp, v2.x, c01[4]); c01[5] = fma2(pp, v2.y, c01[5]);
                        c01[6] = fma2(pp, v3.x, c01[6]); c01[7] = fma2(pp, v3.y, c01[7]);
                    }
                }
            }
            __syncthreads();
        }

        float lse = m_r + __logf(l_r);
        float il = 1.f / l_r;
        if (pass == 0) {
            lse_l = lse;
#pragma unroll
            for (int i = 0; i < 8; i++) {
                float2 c = unpack2f(c01[i]);
                ctxl[2 * i] = c.x * il; ctxl[2 * i + 1] = c.y * il;
            }
        } else {
            float p = 1.f / (1.f + __expf(lse - lse_l));
            float o[16];
#pragma unroll
            for (int i = 0; i < 8; i++) {
                float2 c = unpack2f(c01[i]);
                float cg0 = c.x * il, cg1 = c.y * il;
                o[2 * i] = cg0 + p * (ctxl[2 * i] - cg0);
                o[2 * i + 1] = cg1 + p * (ctxl[2 * i + 1] - cg1);
            }
            float4* o4 = reinterpret_cast<float4*>(
                out + ((size_t)(n * T + t0 + qB)) * HID + h * D + dg * 16);
            o4[0] = make_float4(o[0], o[1], o[2], o[3]);
            o4[1] = make_float4(o[4], o[5], o[6], o[7]);
            o4[2] = make_float4(o[8], o[9], o[10], o[11]);
            o4[3] = make_float4(o[12], o[13], o[14], o[15]);
        }
        __syncthreads();
    }
}

// ---- BOS row: full UNSCALED attention over all 4096 keys, overwrites t=0 ----
__global__ __launch_bounds__(256) void bos_kernel(
    const float* __restrict__ mask, float* __restrict__ out)
{
    __shared__ __align__(16) float q0s[64];
    __shared__ float sc[T];
    __shared__ float red[256];

    int h = blockIdx.x & 15, n = blockIdx.x >> 4;
    size_t hoff = ((size_t)(n * NH + h)) * T * D;
    const float* Q = g_q + hoff;
    const float* K = g_k + hoff;
    const float* V = g_v + hoff;
    const float* mrow = mask + (size_t)n * T;
    int tid = threadIdx.x;

    if (tid < 16)
        *reinterpret_cast<float4*>(&q0s[tid * 4]) =
            *reinterpret_cast<const float4*>(Q + tid * 4);
    __syncthreads();

    float lmax = -1e30f;
    for (int t = tid; t < T; t += 256) {
        const float* krow = K + (size_t)t * D;
        float s = 0.f;
#pragma unroll
        for (int d = 0; d < 64; d += 4) {
            float4 kv = *reinterpret_cast<const float4*>(krow + d);
            s += q0s[d] * kv.x + q0s[d + 1] * kv.y + q0s[d + 2] * kv.z + q0s[d + 3] * kv.w;
        }
        s += mrow[t];
        sc[t] = s;
        lmax = fmaxf(lmax, s);
    }
    red[tid] = lmax; __syncthreads();
    for (int o = 128; o > 0; o >>= 1) {
        if (tid < o) red[tid] = fmaxf(red[tid], red[tid + o]);
        __syncthreads();
    }
    float mx = red[0];
    __syncthreads();

    float lsum = 0.f;
    for (int t = tid; t < T; t += 256) {
        float e = __expf(sc[t] - mx);
        sc[t] = e;
        lsum += e;
    }
    red[tid] = lsum; __syncthreads();
    for (int o = 128; o > 0; o >>= 1) {
        if (tid < o) red[tid] += red[tid + o];
        __syncthreads();
    }
    float inv = 1.f / red[0];
    __syncthreads();

    int dd = tid & 63, dg = tid >> 6;
    float acc = 0.f;
    for (int t = dg * 1024; t < (dg + 1) * 1024; t++)
        acc += sc[t] * V[(size_t)t * D + dd];
    red[tid] = acc; __syncthreads();
    if (tid < 64) {
        float c = (red[tid] + red[tid + 64] + red[tid + 128] + red[tid + 192]) * inv;
        out[(size_t)n * T * HID + h * D + tid] = c;
    }
}

extern "C" void kernel_launch(void* const* d_in, const int* in_sizes, int n_in,
                              void* d_out, int out_size) {
    const float* hs   = (const float*)d_in[0];
    const float* mask = (const float*)d_in[1];
    const float* Wq = (const float*)d_in[2];
    const float* bq = (const float*)d_in[3];
    const float* Wk = (const float*)d_in[4];
    const float* bk = (const float*)d_in[5];
    const float* Wv = (const float*)d_in[6];
    const float* bv = (const float*)d_in[7];
    float* out = (float*)d_out;

    cudaFuncSetAttribute(gemm_tc, cudaFuncAttributeMaxDynamicSharedMemorySize, SMEM_TOT);

    split_A<<<2048, 256>>>(hs);
    split_W<<<1024, 256>>>(Wq, 0);
    split_W<<<1024, 256>>>(Wk, 1);
    split_W<<<1024, 256>>>(Wv, 2);

    dim3 gg(HID / 128, MTOT / 128);
    gemm_tc<<<gg, 256, SMEM_TOT>>>(hs, Wq, bq, 0);
    gemm_tc<<<gg, 256, SMEM_TOT>>>(hs, Wk, bk, 1);
    gemm_tc<<<gg, 256, SMEM_TOT>>>(hs, Wv, bv, 2);

    topk_kernel<<<NB * NH * 64, 64>>>(bq, mask);
    attn_kernel<<<NB * NH * 64, 256>>>(mask, out);
    bos_kernel<<<NB * NH, 256>>>(mask, out);
}